// round 8
// baseline (speedup 1.0000x reference)
#include <cuda_runtime.h>
#include <cuda_bf16.h>
#include <cstdint>
#include <cstddef>

// Problem constants
#define N_NODES 50000
#define NP      50048          // padded: 782*64 = 391*128
#define NSCAN   50176          // NP + 128, = 196*256 for scan
#define NT      391            // node tiles of 128
#define D       128
#define E_MAX   800000
#define BN_EPS  1e-5f

// ---------------- scratch (static device globals; no runtime alloc) -------------
__device__ float g_x  [(size_t)NP * D];
__device__ float g_m  [(size_t)NP * D];
__device__ float g_as [NP];
__device__ float g_ad [NP];
__device__ float g_g  [(size_t)NP * 768];
__device__ float g_h  [(size_t)NP * D];
__device__ float g_sum[D];
__device__ float g_ssq[D];
__device__ int   g_is64;

// CSR build for edge gather
__device__ int g_cnt [NSCAN];
__device__ int g_off [NSCAN];
__device__ int g_bsum[256];
__device__ int g_boff[256];
__device__ int g_start[NSCAN];
__device__ int g_cur [NSCAN];
__device__ int g_esrc[E_MAX];

// bf16 hi/lo planes for tensor-core GEMMs
__device__ __nv_bfloat16 g_xh  [(size_t)NP * D];
__device__ __nv_bfloat16 g_xl  [(size_t)NP * D];
__device__ __nv_bfloat16 g_agh [(size_t)NP * D];
__device__ __nv_bfloat16 g_agl [(size_t)NP * D];
__device__ __nv_bfloat16 g_wh  [896 * D];   // [W_ih(384); W_hh(384); W_msg^T(128)] hi
__device__ __nv_bfloat16 g_wl  [896 * D];   // lo

__device__ __forceinline__ float sigm(float v) { return 1.f / (1.f + __expf(-v)); }

__device__ __forceinline__ uint32_t smem_u32(const void* p) {
    uint32_t a;
    asm("{ .reg .u64 t; cvta.to.shared.u64 t, %1; cvt.u32.u64 %0, t; }" : "=r"(a) : "l"(p));
    return a;
}
__device__ __forceinline__ void f2bf(float v, __nv_bfloat16& h, __nv_bfloat16& l) {
    h = __float2bfloat16(v);
    l = __float2bfloat16(v - __bfloat162float(h));
}
__device__ __forceinline__ void cpa16(uint32_t dst, const void* src) {
    asm volatile("cp.async.ca.shared.global [%0], [%1], 16;" :: "r"(dst), "l"(src));
}
#define CPA_COMMIT() asm volatile("cp.async.commit_group;" ::: "memory")
#define CPA_WAIT0()  asm volatile("cp.async.wait_group 0;" ::: "memory")
#define CPA_WAIT1()  asm volatile("cp.async.wait_group 1;" ::: "memory")

// =================================================================================
// Kernel 0: detect edge_index dtype (int32 vs int64).
// =================================================================================
__global__ void detect_kernel(const void* ei_raw, int E)
{
    const long long* e64 = (const long long*)ei_raw;
    int n = E < 64 ? E : 64;
    int ok = 1;
    for (int i = 0; i < n; i++) {
        long long v = e64[i];
        if (v < 0 || v >= N_NODES) { ok = 0; break; }
    }
    g_is64 = ok;
}

__device__ __forceinline__ void load_edge(const void* ei_raw, int E, int e,
                                          int& src, int& dst)
{
    if (g_is64) {
        const long long* p = (const long long*)ei_raw;
        src = (int)p[e];
        dst = (int)p[(size_t)E + e];
    } else {
        const int* p = (const int*)ei_raw;
        src = p[e];
        dst = p[E + e];
    }
}

// =================================================================================
// Kernel A: x copy + bf16 planes + attention pre-dots + zeroing.
// =================================================================================
__global__ __launch_bounds__(256) void node_pre_kernel(
    const float* __restrict__ x, const float* __restrict__ W_att)
{
    __shared__ __align__(16) float xs[64][132];
    __shared__ float Was[128], Wad[128];

    const int tid = threadIdx.x;
    const int n0  = blockIdx.x * 64;

    if (tid < 128) { Was[tid] = W_att[tid]; Wad[tid] = W_att[128 + tid]; }
    if (tid < 64) g_cnt[n0 + tid] = 0;
    if (blockIdx.x == 0 && tid < 128) {
        g_sum[tid] = 0.f; g_ssq[tid] = 0.f; g_cnt[NP + tid] = 0;
    }

    for (int i = tid; i < 64 * 32; i += 256) {
        int node = i >> 5, cq = i & 31;
        float4 v = make_float4(0.f, 0.f, 0.f, 0.f);
        int gn = n0 + node;
        if (gn < N_NODES) v = *(const float4*)&x[(size_t)gn * D + cq * 4];
        *(float4*)&xs[node][cq * 4] = v;
        *(float4*)&g_x[(size_t)gn * D + cq * 4] = v;
        __nv_bfloat162 h01, h23, l01, l23;
        f2bf(v.x, h01.x, l01.x); f2bf(v.y, h01.y, l01.y);
        f2bf(v.z, h23.x, l23.x); f2bf(v.w, h23.y, l23.y);
        *(__nv_bfloat162*)&g_xh[(size_t)gn * D + cq * 4]     = h01;
        *(__nv_bfloat162*)&g_xh[(size_t)gn * D + cq * 4 + 2] = h23;
        *(__nv_bfloat162*)&g_xl[(size_t)gn * D + cq * 4]     = l01;
        *(__nv_bfloat162*)&g_xl[(size_t)gn * D + cq * 4 + 2] = l23;
    }
    __syncthreads();

    if (tid < 128) {
        int node = tid >> 1, sel = tid & 1;
        const float* wv = sel ? Wad : Was;
        float a0 = 0.f, a1 = 0.f, a2 = 0.f, a3 = 0.f;
#pragma unroll 8
        for (int k = 0; k < 128; k += 4) {
            a0 += xs[node][k]     * wv[k];
            a1 += xs[node][k + 1] * wv[k + 1];
            a2 += xs[node][k + 2] * wv[k + 2];
            a3 += xs[node][k + 3] * wv[k + 3];
        }
        float r = (a0 + a1) + (a2 + a3);
        if (sel) g_ad[n0 + node] = r; else g_as[n0 + node] = r;
    }
}

// =================================================================================
// Convert weights -> stacked bf16 hi/lo planes.
// Rows 0..383: W_ih; 384..767: W_hh; 768..895: W_msg^T.
// =================================================================================
#define CVT_W_Q (896 * 32)
__global__ __launch_bounds__(256) void convert_w_kernel(
    const float* __restrict__ W_ih, const float* __restrict__ W_hh,
    const float* __restrict__ W_msg)
{
    int idx = blockIdx.x * 256 + threadIdx.x;
    if (idx >= CVT_W_Q) return;
    int row = idx >> 5, cq = idx & 31;
    size_t off = (size_t)row * D + cq * 4;

    float4 v;
    if (row < 384) {
        v = *(const float4*)&W_ih[(size_t)row * D + cq * 4];
    } else if (row < 768) {
        v = *(const float4*)&W_hh[(size_t)(row - 384) * D + cq * 4];
    } else {
        int j = row - 768;
        int k = cq * 4;
        v.x = W_msg[(size_t)(k + 0) * D + j];
        v.y = W_msg[(size_t)(k + 1) * D + j];
        v.z = W_msg[(size_t)(k + 2) * D + j];
        v.w = W_msg[(size_t)(k + 3) * D + j];
    }
    __nv_bfloat162 h01, h23, l01, l23;
    f2bf(v.x, h01.x, l01.x); f2bf(v.y, h01.y, l01.y);
    f2bf(v.z, h23.x, l23.x); f2bf(v.w, h23.y, l23.y);
    *(__nv_bfloat162*)&g_wh[off]     = h01;
    *(__nv_bfloat162*)&g_wh[off + 2] = h23;
    *(__nv_bfloat162*)&g_wl[off]     = l01;
    *(__nv_bfloat162*)&g_wl[off + 2] = l23;
}

// =================================================================================
// CSR build: histogram -> scan (3 kernels) -> scatter.
// =================================================================================
__global__ __launch_bounds__(256) void hist_kernel(const void* __restrict__ ei, int E)
{
    int e = blockIdx.x * 256 + threadIdx.x;
    if (e >= E) return;
    int src, dst;
    load_edge(ei, E, e, src, dst);
    if ((unsigned)dst >= N_NODES) return;
    atomicAdd(&g_cnt[dst], 1);
}

__global__ __launch_bounds__(256) void scan_a_kernel()
{
    __shared__ int sh[256];
    const int tid = threadIdx.x;
    int t = blockIdx.x * 256 + tid;
    int v = g_cnt[t];
    sh[tid] = v; __syncthreads();
#pragma unroll
    for (int o = 1; o < 256; o <<= 1) {
        int u = (tid >= o) ? sh[tid - o] : 0;
        __syncthreads();
        sh[tid] += u;
        __syncthreads();
    }
    g_off[t] = sh[tid] - v;
    if (tid == 255) g_bsum[blockIdx.x] = sh[255];
}

__global__ __launch_bounds__(256) void scan_b_kernel()
{
    __shared__ int sh[256];
    const int tid = threadIdx.x;
    int v = (tid < NSCAN / 256) ? g_bsum[tid] : 0;
    sh[tid] = v; __syncthreads();
#pragma unroll
    for (int o = 1; o < 256; o <<= 1) {
        int u = (tid >= o) ? sh[tid - o] : 0;
        __syncthreads();
        sh[tid] += u;
        __syncthreads();
    }
    g_boff[tid] = sh[tid] - v;
}

__global__ __launch_bounds__(256) void scan_c_kernel()
{
    int t = blockIdx.x * 256 + threadIdx.x;
    int s = g_off[t] + g_boff[blockIdx.x];
    g_start[t] = s;
    g_cur[t]   = s;
}

__global__ __launch_bounds__(256) void scatter_kernel(const void* __restrict__ ei, int E)
{
    int e = blockIdx.x * 256 + threadIdx.x;
    if (e >= E) return;
    int src, dst;
    load_edge(ei, E, e, src, dst);
    if ((unsigned)src >= N_NODES || (unsigned)dst >= N_NODES) return;
    int p = atomicAdd(&g_cur[dst], 1);
    if (p < E) g_esrc[p] = src;
}

// =================================================================================
// Gather: one warp per dst node; writes agg directly as bf16 hi/lo planes.
// =================================================================================
__global__ __launch_bounds__(256) void gather_kernel(const float* __restrict__ b_att)
{
    const int wid  = threadIdx.x >> 5;
    const int lane = threadIdx.x & 31;
    const int n = blockIdx.x * 8 + wid;
    if (n >= NP) return;

    const int s0 = g_start[n];
    const int s1 = g_start[n + 1];
    const float adb = ((n < N_NODES) ? g_ad[n] : 0.f) + b_att[0];

    float4 acc = make_float4(0.f, 0.f, 0.f, 0.f);
    int i = s0;
    for (; i + 1 < s1; i += 2) {
        int src0 = g_esrc[i], src1 = g_esrc[i + 1];
        float at0 = sigm(g_as[src0] + adb);
        float at1 = sigm(g_as[src1] + adb);
        float4 v0 = *(const float4*)&g_m[(size_t)src0 * D + lane * 4];
        float4 v1 = *(const float4*)&g_m[(size_t)src1 * D + lane * 4];
        acc.x += v0.x * at0 + v1.x * at1;
        acc.y += v0.y * at0 + v1.y * at1;
        acc.z += v0.z * at0 + v1.z * at1;
        acc.w += v0.w * at0 + v1.w * at1;
    }
    if (i < s1) {
        int src0 = g_esrc[i];
        float at0 = sigm(g_as[src0] + adb);
        float4 v0 = *(const float4*)&g_m[(size_t)src0 * D + lane * 4];
        acc.x += v0.x * at0; acc.y += v0.y * at0;
        acc.z += v0.z * at0; acc.w += v0.w * at0;
    }
    __nv_bfloat162 h01, h23, l01, l23;
    f2bf(acc.x, h01.x, l01.x); f2bf(acc.y, h01.y, l01.y);
    f2bf(acc.z, h23.x, l23.x); f2bf(acc.w, h23.y, l23.y);
    size_t o = (size_t)n * D + lane * 4;
    *(__nv_bfloat162*)&g_agh[o]     = h01;
    *(__nv_bfloat162*)&g_agh[o + 2] = h23;
    *(__nv_bfloat162*)&g_agl[o]     = l01;
    *(__nv_bfloat162*)&g_agl[o + 2] = l23;
}

// =================================================================================
// Persistent split-bf16 GEMM: B resident in SMEM, A tiles double-buffered cp.async.
// SMEM: sB[128][264] (hi|lo) + sA[2][128][264]. 8 warps 4(M)x2(N), warp 32x64.
// =================================================================================
#define AS_STR 264
#define SMEM_GEMM (3 * 128 * AS_STR * 2)

__device__ __forceinline__ void mma16816(float* c, const uint32_t* a, const uint32_t* b) {
    asm volatile(
        "mma.sync.aligned.m16n8k16.row.col.f32.bf16.bf16.f32 "
        "{%0,%1,%2,%3}, {%4,%5,%6,%7}, {%8,%9}, {%0,%1,%2,%3};"
        : "+f"(c[0]), "+f"(c[1]), "+f"(c[2]), "+f"(c[3])
        : "r"(a[0]), "r"(a[1]), "r"(a[2]), "r"(a[3]), "r"(b[0]), "r"(b[1]));
}
__device__ __forceinline__ void ldmx4(uint32_t* d, uint32_t addr) {
    asm volatile("ldmatrix.sync.aligned.m8n8.x4.shared.b16 {%0,%1,%2,%3}, [%4];"
                 : "=r"(d[0]), "=r"(d[1]), "=r"(d[2]), "=r"(d[3]) : "r"(addr));
}

// async-load one A tile (hi+lo planes) into buffer at byte address sa_b
__device__ __forceinline__ void issue_A(
    const __nv_bfloat16* __restrict__ Ah, const __nv_bfloat16* __restrict__ Al,
    int n0, uint32_t sa_b, int tid)
{
#pragma unroll
    for (int it = 0; it < 8; it++) {
        int i = tid + it * 256;
        int row = i >> 4, col = (i & 15) * 8;
        uint32_t d = sa_b + (uint32_t)(row * AS_STR + col) * 2;
        size_t gs = (size_t)(n0 + row) * D + col;
        cpa16(d, &Ah[gs]);
        cpa16(d + 256, &Al[gs]);
    }
}

// compute one 128x128 tile from sA (byte addr base given as pointer) and sB
__device__ __forceinline__ void gemm_tile(
    const __nv_bfloat16* sA, const __nv_bfloat16* sB,
    const float* __restrict__ bias, float* __restrict__ out,
    int ostride, int ocol0, int n0)
{
    const int tid  = threadIdx.x;
    const int wid  = tid >> 5;
    const int lane = tid & 31;
    const int wm = (wid & 3) * 32;
    const int wn = (wid >> 2) * 64;
    const int g  = lane >> 3;
    const int r  = lane & 7;
    const int qr = lane >> 2;
    const int qc = (lane & 3) * 2;

    uint32_t aBase[2], bBase[4];
#pragma unroll
    for (int mt = 0; mt < 2; mt++) {
        int row = wm + mt * 16 + ((g & 1) ? 8 : 0) + r;
        int col = (g >= 2) ? 8 : 0;
        aBase[mt] = smem_u32(&sA[row * AS_STR + col]);
    }
#pragma unroll
    for (int ntp = 0; ntp < 4; ntp++) {
        int row = wn + (ntp * 2 + (g >> 1)) * 8 + r;
        int col = (g & 1) ? 8 : 0;
        bBase[ntp] = smem_u32(&sB[row * AS_STR + col]);
    }

    float c[2][8][4];
#pragma unroll
    for (int mt = 0; mt < 2; mt++)
#pragma unroll
        for (int nt = 0; nt < 8; nt++)
#pragma unroll
            for (int j = 0; j < 4; j++) c[mt][nt][j] = 0.f;

#pragma unroll
    for (int pass = 0; pass < 3; pass++) {
        const int kA = (pass == 1) ? 128 : 0;
        const int kB = (pass == 2) ? 128 : 0;
#pragma unroll
        for (int s = 0; s < 8; s++) {
            const uint32_t offA = (uint32_t)((kA + s * 16) * 2);
            const uint32_t offB = (uint32_t)((kB + s * 16) * 2);
            uint32_t a[2][4], b[4][4];
            ldmx4(a[0], aBase[0] + offA);
            ldmx4(a[1], aBase[1] + offA);
#pragma unroll
            for (int ntp = 0; ntp < 4; ntp++) ldmx4(b[ntp], bBase[ntp] + offB);
#pragma unroll
            for (int mt = 0; mt < 2; mt++)
#pragma unroll
                for (int ntp = 0; ntp < 4; ntp++) {
                    mma16816(c[mt][ntp * 2],     a[mt], &b[ntp][0]);
                    mma16816(c[mt][ntp * 2 + 1], a[mt], &b[ntp][2]);
                }
        }
    }

#pragma unroll
    for (int mt = 0; mt < 2; mt++) {
#pragma unroll
        for (int nt = 0; nt < 8; nt++) {
            int col = wn + nt * 8 + qc;
            float b0 = bias[col], b1 = bias[col + 1];
            int r0 = n0 + wm + mt * 16 + qr;
            size_t g0 = (size_t)r0 * ostride + ocol0 + col;
            size_t g1 = (size_t)(r0 + 8) * ostride + ocol0 + col;
            *(float2*)&out[g0] = make_float2(c[mt][nt][0] + b0, c[mt][nt][1] + b1);
            *(float2*)&out[g1] = make_float2(c[mt][nt][2] + b0, c[mt][nt][3] + b1);
        }
    }
}

// persistent driver: one B group resident, loop tiles t = t0, t0+PB, ...
__device__ __forceinline__ void gemm_persist(
    const __nv_bfloat16* __restrict__ Ah, const __nv_bfloat16* __restrict__ Al,
    int brow0, const float* __restrict__ bias, float* __restrict__ out,
    int ostride, int ocol0, int t0, int PB, __nv_bfloat16* smem)
{
    __nv_bfloat16* sB  = smem;
    __nv_bfloat16* sA0 = smem + 128 * AS_STR;
    __nv_bfloat16* sA1 = smem + 2 * 128 * AS_STR;
    const int tid = threadIdx.x;

    // load B planes (resident for kernel lifetime)
#pragma unroll
    for (int it = 0; it < 8; it++) {
        int i = tid + it * 256;
        int row = i >> 4, col = (i & 15) * 8;
        size_t gb = (size_t)(brow0 + row) * D + col;
        *(uint4*)&sB[row * AS_STR + col]       = *(const uint4*)&g_wh[gb];
        *(uint4*)&sB[row * AS_STR + 128 + col] = *(const uint4*)&g_wl[gb];
    }
    if (t0 >= NT) return;

    issue_A(Ah, Al, t0 * 128, smem_u32(sA0), tid);
    CPA_COMMIT();

    int s = 0;
    for (int t = t0; t < NT; t += PB, s ^= 1) {
        __nv_bfloat16* cur = s ? sA1 : sA0;
        __nv_bfloat16* nxt = s ? sA0 : sA1;
        int tn = t + PB;
        if (tn < NT) {
            issue_A(Ah, Al, tn * 128, smem_u32(nxt), tid);
            CPA_COMMIT();
            CPA_WAIT1();
        } else {
            CPA_WAIT0();
        }
        __syncthreads();
        gemm_tile(cur, sB, bias, out, ostride, ocol0, t * 128);
        __syncthreads();
    }
}

#define PB_MAIN 24
#define PB_MSG  144

__global__ __launch_bounds__(256) void gemm_main_kernel(
    const float* __restrict__ b_ih, const float* __restrict__ b_hh)
{
    extern __shared__ __align__(16) __nv_bfloat16 smem[];
    const int bx = blockIdx.x;
    const bool ih = (bx < 3);
    gemm_persist(ih ? g_agh : g_xh, ih ? g_agl : g_xl,
                 bx * 128,
                 ih ? (b_ih + bx * 128) : (b_hh + (bx - 3) * 128),
                 g_g, 768, bx * 128, blockIdx.y, PB_MAIN, smem);
}

__global__ __launch_bounds__(256) void gemm_msg_kernel(const float* __restrict__ b_msg)
{
    extern __shared__ __align__(16) __nv_bfloat16 smem[];
    gemm_persist(g_xh, g_xl, 768, b_msg, g_m, 128, 0, blockIdx.x, PB_MSG, smem);
}

// =================================================================================
// Kernel D: GRU elementwise + BN column-stat accumulation.
// =================================================================================
__global__ __launch_bounds__(256) void gru_kernel(const float* __restrict__ x)
{
    __shared__ float rs_[8][128];
    __shared__ float rq_[8][128];

    const int tid = threadIdx.x;
    const int c4 = tid & 31;
    const int rs = tid >> 5;
    float4 s = make_float4(0.f, 0.f, 0.f, 0.f);
    float4 q = make_float4(0.f, 0.f, 0.f, 0.f);

    for (int it = 0; it < 16; it++) {
        int n = blockIdx.x * 128 + it * 8 + rs;
        if (n >= N_NODES) break;
        size_t gb = (size_t)n * 768 + c4 * 4;
        float4 ir = *(const float4*)&g_g[gb];
        float4 iz = *(const float4*)&g_g[gb + 128];
        float4 in_ = *(const float4*)&g_g[gb + 256];
        float4 hr = *(const float4*)&g_g[gb + 384];
        float4 hz = *(const float4*)&g_g[gb + 512];
        float4 hn = *(const float4*)&g_g[gb + 640];
        float4 xv = *(const float4*)&x[(size_t)n * D + c4 * 4];

        float4 h;
        {
            float r = sigm(ir.x + hr.x), z = sigm(iz.x + hz.x);
            float nn = tanhf(in_.x + r * hn.x); h.x = (1.f - z) * nn + z * xv.x;
        }
        {
            float r = sigm(ir.y + hr.y), z = sigm(iz.y + hz.y);
            float nn = tanhf(in_.y + r * hn.y); h.y = (1.f - z) * nn + z * xv.y;
        }
        {
            float r = sigm(ir.z + hr.z), z = sigm(iz.z + hz.z);
            float nn = tanhf(in_.z + r * hn.z); h.z = (1.f - z) * nn + z * xv.z;
        }
        {
            float r = sigm(ir.w + hr.w), z = sigm(iz.w + hz.w);
            float nn = tanhf(in_.w + r * hn.w); h.w = (1.f - z) * nn + z * xv.w;
        }
        *(float4*)&g_h[(size_t)n * D + c4 * 4] = h;
        s.x += h.x; s.y += h.y; s.z += h.z; s.w += h.w;
        q.x += h.x * h.x; q.y += h.y * h.y; q.z += h.z * h.z; q.w += h.w * h.w;
    }

    *(float4*)&rs_[rs][c4 * 4] = s;
    *(float4*)&rq_[rs][c4 * 4] = q;
    __syncthreads();
    if (tid < 128) {
        float a = 0.f, b = 0.f;
#pragma unroll
        for (int r = 0; r < 8; r++) { a += rs_[r][tid]; b += rq_[r][tid]; }
        atomicAdd(&g_sum[tid], a);
        atomicAdd(&g_ssq[tid], b);
    }
}

// =================================================================================
// Kernel E: BatchNorm normalize.
// =================================================================================
__global__ __launch_bounds__(256) void bn_kernel(
    const float* __restrict__ gamma, const float* __restrict__ beta,
    float* __restrict__ out)
{
    int idx = blockIdx.x * 256 + threadIdx.x;
    if (idx >= N_NODES * 32) return;
    int c4 = idx & 31;
    const float inv_n = 1.f / (float)N_NODES;

    float4 h  = *(const float4*)&g_h[(size_t)idx * 4];
    float4 sm = *(const float4*)&g_sum[c4 * 4];
    float4 sq = *(const float4*)&g_ssq[c4 * 4];
    float4 ga = *(const float4*)&gamma[c4 * 4];
    float4 be = *(const float4*)&beta[c4 * 4];

    float4 o;
    {
        float mean = sm.x * inv_n; float var = sq.x * inv_n - mean * mean;
        o.x = ga.x * (h.x - mean) * rsqrtf(var + BN_EPS) + be.x;
    }
    {
        float mean = sm.y * inv_n; float var = sq.y * inv_n - mean * mean;
        o.y = ga.y * (h.y - mean) * rsqrtf(var + BN_EPS) + be.y;
    }
    {
        float mean = sm.z * inv_n; float var = sq.z * inv_n - mean * mean;
        o.z = ga.z * (h.z - mean) * rsqrtf(var + BN_EPS) + be.z;
    }
    {
        float mean = sm.w * inv_n; float var = sq.w * inv_n - mean * mean;
        o.w = ga.w * (h.w - mean) * rsqrtf(var + BN_EPS) + be.w;
    }
    *(float4*)&out[(size_t)idx * 4] = o;
}

// =================================================================================
extern "C" void kernel_launch(void* const* d_in, const int* in_sizes, int n_in,
                              void* d_out, int out_size)
{
    const float* x     = (const float*)d_in[0];
    const void*  ei    = d_in[1];
    const float* W_msg = (const float*)d_in[2];
    const float* b_msg = (const float*)d_in[3];
    const float* W_att = (const float*)d_in[4];
    const float* b_att = (const float*)d_in[5];
    const float* W_ih  = (const float*)d_in[6];
    const float* b_ih  = (const float*)d_in[7];
    const float* W_hh  = (const float*)d_in[8];
    const float* b_hh  = (const float*)d_in[9];
    const float* gamma = (const float*)d_in[10];
    const float* beta  = (const float*)d_in[11];
    float* out = (float*)d_out;

    const int E = in_sizes[1] / 2;

    static int smem_set = 0;
    if (!smem_set) {
        cudaFuncSetAttribute(gemm_main_kernel,
                             cudaFuncAttributeMaxDynamicSharedMemorySize, SMEM_GEMM);
        cudaFuncSetAttribute(gemm_msg_kernel,
                             cudaFuncAttributeMaxDynamicSharedMemorySize, SMEM_GEMM);
        smem_set = 1;
    }

    detect_kernel<<<1, 1>>>(ei, E);
    node_pre_kernel<<<NP / 64, 256>>>(x, W_att);
    convert_w_kernel<<<(CVT_W_Q + 255) / 256, 256>>>(W_ih, W_hh, W_msg);
    gemm_msg_kernel<<<PB_MSG, 256, SMEM_GEMM>>>(b_msg);
    hist_kernel<<<(E + 255) / 256, 256>>>(ei, E);
    scan_a_kernel<<<NSCAN / 256, 256>>>();
    scan_b_kernel<<<1, 256>>>();
    scan_c_kernel<<<NSCAN / 256, 256>>>();
    scatter_kernel<<<(E + 255) / 256, 256>>>(ei, E);
    gather_kernel<<<(NP + 7) / 8, 256>>>(b_att);
    gemm_main_kernel<<<dim3(6, PB_MAIN), 256, SMEM_GEMM>>>(b_ih, b_hh);
    gru_kernel<<<NP / 128, 256>>>(x);
    bn_kernel<<<(N_NODES * 32 + 255) / 256, 256>>>(gamma, beta, out);
}

// round 9
// speedup vs baseline: 1.3650x; 1.3650x over previous
#include <cuda_runtime.h>
#include <cuda_bf16.h>
#include <cstdint>
#include <cstddef>

// Problem constants
#define N_NODES 50000
#define NP      50048          // padded: 782*64 = 391*128
#define NSCAN   50176          // NP + 128, = 196*256 for scan
#define NT      391            // node tiles of 128
#define D       128
#define E_MAX   800000
#define BN_EPS  1e-5f

// ---------------- scratch (static device globals; no runtime alloc) -------------
__device__ float g_x  [(size_t)NP * D];
__device__ float g_m  [(size_t)NP * D];
__device__ float g_as [NP];
__device__ float g_ad [NP];
__device__ float g_g  [(size_t)NP * 768];
__device__ float g_h  [(size_t)NP * D];
__device__ float g_sum[D];
__device__ float g_ssq[D];
__device__ int   g_is64;

// CSR build for edge gather
__device__ int g_cnt [NSCAN];
__device__ int g_off [NSCAN];
__device__ int g_bsum[256];
__device__ int g_boff[256];
__device__ int g_start[NSCAN];
__device__ int g_cur [NSCAN];
__device__ int g_esrc[E_MAX];

// bf16 hi/lo planes for tensor-core GEMMs
__device__ __nv_bfloat16 g_xh  [(size_t)NP * D];
__device__ __nv_bfloat16 g_xl  [(size_t)NP * D];
__device__ __nv_bfloat16 g_agh [(size_t)NP * D];
__device__ __nv_bfloat16 g_agl [(size_t)NP * D];
__device__ __nv_bfloat16 g_wh  [896 * D];   // [W_ih(384); W_hh(384); W_msg^T(128)] hi
__device__ __nv_bfloat16 g_wl  [896 * D];   // lo

__device__ __forceinline__ float sigm(float v) { return 1.f / (1.f + __expf(-v)); }

__device__ __forceinline__ uint32_t smem_u32(const void* p) {
    uint32_t a;
    asm("{ .reg .u64 t; cvta.to.shared.u64 t, %1; cvt.u32.u64 %0, t; }" : "=r"(a) : "l"(p));
    return a;
}
__device__ __forceinline__ void f2bf(float v, __nv_bfloat16& h, __nv_bfloat16& l) {
    h = __float2bfloat16(v);
    l = __float2bfloat16(v - __bfloat162float(h));
}
__device__ __forceinline__ void cpa16(uint32_t dst, const void* src) {
    asm volatile("cp.async.ca.shared.global [%0], [%1], 16;" :: "r"(dst), "l"(src));
}
#define CPA_COMMIT() asm volatile("cp.async.commit_group;" ::: "memory")
#define CPA_WAIT0()  asm volatile("cp.async.wait_group 0;" ::: "memory")
#define CPA_WAIT1()  asm volatile("cp.async.wait_group 1;" ::: "memory")

// =================================================================================
// Kernel 0: detect edge_index dtype (int32 vs int64).
// =================================================================================
__global__ void detect_kernel(const void* ei_raw, int E)
{
    const long long* e64 = (const long long*)ei_raw;
    int n = E < 64 ? E : 64;
    int ok = 1;
    for (int i = 0; i < n; i++) {
        long long v = e64[i];
        if (v < 0 || v >= N_NODES) { ok = 0; break; }
    }
    g_is64 = ok;
}

__device__ __forceinline__ void load_edge(const void* ei_raw, int E, int e,
                                          int& src, int& dst)
{
    if (g_is64) {
        const long long* p = (const long long*)ei_raw;
        src = (int)p[e];
        dst = (int)p[(size_t)E + e];
    } else {
        const int* p = (const int*)ei_raw;
        src = p[e];
        dst = p[E + e];
    }
}

// =================================================================================
// Kernel A: x copy + bf16 planes + attention pre-dots + zeroing.
// =================================================================================
__global__ __launch_bounds__(256) void node_pre_kernel(
    const float* __restrict__ x, const float* __restrict__ W_att)
{
    __shared__ __align__(16) float xs[64][132];
    __shared__ float Was[128], Wad[128];

    const int tid = threadIdx.x;
    const int n0  = blockIdx.x * 64;

    if (tid < 128) { Was[tid] = W_att[tid]; Wad[tid] = W_att[128 + tid]; }
    if (tid < 64) g_cnt[n0 + tid] = 0;
    if (blockIdx.x == 0 && tid < 128) {
        g_sum[tid] = 0.f; g_ssq[tid] = 0.f; g_cnt[NP + tid] = 0;
    }

    for (int i = tid; i < 64 * 32; i += 256) {
        int node = i >> 5, cq = i & 31;
        float4 v = make_float4(0.f, 0.f, 0.f, 0.f);
        int gn = n0 + node;
        if (gn < N_NODES) v = *(const float4*)&x[(size_t)gn * D + cq * 4];
        *(float4*)&xs[node][cq * 4] = v;
        *(float4*)&g_x[(size_t)gn * D + cq * 4] = v;
        __nv_bfloat162 h01, h23, l01, l23;
        f2bf(v.x, h01.x, l01.x); f2bf(v.y, h01.y, l01.y);
        f2bf(v.z, h23.x, l23.x); f2bf(v.w, h23.y, l23.y);
        *(__nv_bfloat162*)&g_xh[(size_t)gn * D + cq * 4]     = h01;
        *(__nv_bfloat162*)&g_xh[(size_t)gn * D + cq * 4 + 2] = h23;
        *(__nv_bfloat162*)&g_xl[(size_t)gn * D + cq * 4]     = l01;
        *(__nv_bfloat162*)&g_xl[(size_t)gn * D + cq * 4 + 2] = l23;
    }
    __syncthreads();

    if (tid < 128) {
        int node = tid >> 1, sel = tid & 1;
        const float* wv = sel ? Wad : Was;
        float a0 = 0.f, a1 = 0.f, a2 = 0.f, a3 = 0.f;
#pragma unroll 8
        for (int k = 0; k < 128; k += 4) {
            a0 += xs[node][k]     * wv[k];
            a1 += xs[node][k + 1] * wv[k + 1];
            a2 += xs[node][k + 2] * wv[k + 2];
            a3 += xs[node][k + 3] * wv[k + 3];
        }
        float r = (a0 + a1) + (a2 + a3);
        if (sel) g_ad[n0 + node] = r; else g_as[n0 + node] = r;
    }
}

// =================================================================================
// Convert weights -> stacked bf16 hi/lo planes.
// Rows 0..383: W_ih; 384..767: W_hh; 768..895: W_msg^T.
// =================================================================================
#define CVT_W_Q (896 * 32)
__global__ __launch_bounds__(256) void convert_w_kernel(
    const float* __restrict__ W_ih, const float* __restrict__ W_hh,
    const float* __restrict__ W_msg)
{
    int idx = blockIdx.x * 256 + threadIdx.x;
    if (idx >= CVT_W_Q) return;
    int row = idx >> 5, cq = idx & 31;
    size_t off = (size_t)row * D + cq * 4;

    float4 v;
    if (row < 384) {
        v = *(const float4*)&W_ih[(size_t)row * D + cq * 4];
    } else if (row < 768) {
        v = *(const float4*)&W_hh[(size_t)(row - 384) * D + cq * 4];
    } else {
        int j = row - 768;
        int k = cq * 4;
        v.x = W_msg[(size_t)(k + 0) * D + j];
        v.y = W_msg[(size_t)(k + 1) * D + j];
        v.z = W_msg[(size_t)(k + 2) * D + j];
        v.w = W_msg[(size_t)(k + 3) * D + j];
    }
    __nv_bfloat162 h01, h23, l01, l23;
    f2bf(v.x, h01.x, l01.x); f2bf(v.y, h01.y, l01.y);
    f2bf(v.z, h23.x, l23.x); f2bf(v.w, h23.y, l23.y);
    *(__nv_bfloat162*)&g_wh[off]     = h01;
    *(__nv_bfloat162*)&g_wh[off + 2] = h23;
    *(__nv_bfloat162*)&g_wl[off]     = l01;
    *(__nv_bfloat162*)&g_wl[off + 2] = l23;
}

// =================================================================================
// CSR build: histogram -> scan (3 kernels) -> scatter.
// =================================================================================
__global__ __launch_bounds__(256) void hist_kernel(const void* __restrict__ ei, int E)
{
    int e = blockIdx.x * 256 + threadIdx.x;
    if (e >= E) return;
    int src, dst;
    load_edge(ei, E, e, src, dst);
    if ((unsigned)dst >= N_NODES) return;
    atomicAdd(&g_cnt[dst], 1);
}

__global__ __launch_bounds__(256) void scan_a_kernel()
{
    __shared__ int sh[256];
    const int tid = threadIdx.x;
    int t = blockIdx.x * 256 + tid;
    int v = g_cnt[t];
    sh[tid] = v; __syncthreads();
#pragma unroll
    for (int o = 1; o < 256; o <<= 1) {
        int u = (tid >= o) ? sh[tid - o] : 0;
        __syncthreads();
        sh[tid] += u;
        __syncthreads();
    }
    g_off[t] = sh[tid] - v;
    if (tid == 255) g_bsum[blockIdx.x] = sh[255];
}

__global__ __launch_bounds__(256) void scan_b_kernel()
{
    __shared__ int sh[256];
    const int tid = threadIdx.x;
    int v = (tid < NSCAN / 256) ? g_bsum[tid] : 0;
    sh[tid] = v; __syncthreads();
#pragma unroll
    for (int o = 1; o < 256; o <<= 1) {
        int u = (tid >= o) ? sh[tid - o] : 0;
        __syncthreads();
        sh[tid] += u;
        __syncthreads();
    }
    g_boff[tid] = sh[tid] - v;
}

__global__ __launch_bounds__(256) void scan_c_kernel()
{
    int t = blockIdx.x * 256 + threadIdx.x;
    int s = g_off[t] + g_boff[blockIdx.x];
    g_start[t] = s;
    g_cur[t]   = s;
}

__global__ __launch_bounds__(256) void scatter_kernel(const void* __restrict__ ei, int E)
{
    int e = blockIdx.x * 256 + threadIdx.x;
    if (e >= E) return;
    int src, dst;
    load_edge(ei, E, e, src, dst);
    if ((unsigned)src >= N_NODES || (unsigned)dst >= N_NODES) return;
    int p = atomicAdd(&g_cur[dst], 1);
    if (p < E) g_esrc[p] = src;
}

// =================================================================================
// Gather: one warp per dst node; writes agg directly as bf16 hi/lo planes.
// =================================================================================
__global__ __launch_bounds__(256) void gather_kernel(const float* __restrict__ b_att)
{
    const int wid  = threadIdx.x >> 5;
    const int lane = threadIdx.x & 31;
    const int n = blockIdx.x * 8 + wid;
    if (n >= NP) return;

    const int s0 = g_start[n];
    const int s1 = g_start[n + 1];
    const float adb = ((n < N_NODES) ? g_ad[n] : 0.f) + b_att[0];

    float4 acc = make_float4(0.f, 0.f, 0.f, 0.f);
    int i = s0;
    for (; i + 1 < s1; i += 2) {
        int src0 = g_esrc[i], src1 = g_esrc[i + 1];
        float at0 = sigm(g_as[src0] + adb);
        float at1 = sigm(g_as[src1] + adb);
        float4 v0 = *(const float4*)&g_m[(size_t)src0 * D + lane * 4];
        float4 v1 = *(const float4*)&g_m[(size_t)src1 * D + lane * 4];
        acc.x += v0.x * at0 + v1.x * at1;
        acc.y += v0.y * at0 + v1.y * at1;
        acc.z += v0.z * at0 + v1.z * at1;
        acc.w += v0.w * at0 + v1.w * at1;
    }
    if (i < s1) {
        int src0 = g_esrc[i];
        float at0 = sigm(g_as[src0] + adb);
        float4 v0 = *(const float4*)&g_m[(size_t)src0 * D + lane * 4];
        acc.x += v0.x * at0; acc.y += v0.y * at0;
        acc.z += v0.z * at0; acc.w += v0.w * at0;
    }
    __nv_bfloat162 h01, h23, l01, l23;
    f2bf(acc.x, h01.x, l01.x); f2bf(acc.y, h01.y, l01.y);
    f2bf(acc.z, h23.x, l23.x); f2bf(acc.w, h23.y, l23.y);
    size_t o = (size_t)n * D + lane * 4;
    *(__nv_bfloat162*)&g_agh[o]     = h01;
    *(__nv_bfloat162*)&g_agh[o + 2] = h23;
    *(__nv_bfloat162*)&g_agl[o]     = l01;
    *(__nv_bfloat162*)&g_agl[o + 2] = l23;
}

// =================================================================================
// Split-bf16 GEMM, pair-tile version: per block, B resident + TWO node tiles,
// A1 loads (cp.async) overlap tile0 compute. Accumulators live only inside
// gemm_tile (prevents R8's register blowup).
// =================================================================================
#define AS_STR 264
#define SMEM_GEMM (3 * 128 * AS_STR * 2)

__device__ __forceinline__ void mma16816(float* c, const uint32_t* a, const uint32_t* b) {
    asm volatile(
        "mma.sync.aligned.m16n8k16.row.col.f32.bf16.bf16.f32 "
        "{%0,%1,%2,%3}, {%4,%5,%6,%7}, {%8,%9}, {%0,%1,%2,%3};"
        : "+f"(c[0]), "+f"(c[1]), "+f"(c[2]), "+f"(c[3])
        : "r"(a[0]), "r"(a[1]), "r"(a[2]), "r"(a[3]), "r"(b[0]), "r"(b[1]));
}
__device__ __forceinline__ void ldmx4(uint32_t* d, uint32_t addr) {
    asm volatile("ldmatrix.sync.aligned.m8n8.x4.shared.b16 {%0,%1,%2,%3}, [%4];"
                 : "=r"(d[0]), "=r"(d[1]), "=r"(d[2]), "=r"(d[3]) : "r"(addr));
}

// async-load one 128-row tile (hi+lo planes) into smem at byte address s_b
__device__ __forceinline__ void issue_tile(
    const __nv_bfloat16* __restrict__ Ph, const __nv_bfloat16* __restrict__ Pl,
    int row0, uint32_t s_b, int tid)
{
#pragma unroll
    for (int it = 0; it < 8; it++) {
        int i = tid + it * 256;
        int row = i >> 4, col = (i & 15) * 8;
        uint32_t d = s_b + (uint32_t)(row * AS_STR + col) * 2;
        size_t gs = (size_t)(row0 + row) * D + col;
        cpa16(d, &Ph[gs]);
        cpa16(d + 256, &Pl[gs]);
    }
}

// compute one 128x128 tile from sA and sB; accumulators fully local.
__device__ __forceinline__ void gemm_tile(
    const __nv_bfloat16* sA, const __nv_bfloat16* sB,
    const float* __restrict__ bias, float* __restrict__ out,
    int ostride, int ocol0, int n0)
{
    const int tid  = threadIdx.x;
    const int wid  = tid >> 5;
    const int lane = tid & 31;
    const int wm = (wid & 3) * 32;
    const int wn = (wid >> 2) * 64;
    const int g  = lane >> 3;
    const int r  = lane & 7;
    const int qr = lane >> 2;
    const int qc = (lane & 3) * 2;

    uint32_t aBase[2], bBase[4];
#pragma unroll
    for (int mt = 0; mt < 2; mt++) {
        int row = wm + mt * 16 + ((g & 1) ? 8 : 0) + r;
        int col = (g >= 2) ? 8 : 0;
        aBase[mt] = smem_u32(&sA[row * AS_STR + col]);
    }
#pragma unroll
    for (int ntp = 0; ntp < 4; ntp++) {
        int row = wn + (ntp * 2 + (g >> 1)) * 8 + r;
        int col = (g & 1) ? 8 : 0;
        bBase[ntp] = smem_u32(&sB[row * AS_STR + col]);
    }

    float c[2][8][4];
#pragma unroll
    for (int mt = 0; mt < 2; mt++)
#pragma unroll
        for (int nt = 0; nt < 8; nt++)
#pragma unroll
            for (int j = 0; j < 4; j++) c[mt][nt][j] = 0.f;

#pragma unroll
    for (int pass = 0; pass < 3; pass++) {
        const int kA = (pass == 1) ? 128 : 0;
        const int kB = (pass == 2) ? 128 : 0;
#pragma unroll
        for (int s = 0; s < 8; s++) {
            const uint32_t offA = (uint32_t)((kA + s * 16) * 2);
            const uint32_t offB = (uint32_t)((kB + s * 16) * 2);
            uint32_t a[2][4], b[4][4];
            ldmx4(a[0], aBase[0] + offA);
            ldmx4(a[1], aBase[1] + offA);
#pragma unroll
            for (int ntp = 0; ntp < 4; ntp++) ldmx4(b[ntp], bBase[ntp] + offB);
#pragma unroll
            for (int mt = 0; mt < 2; mt++)
#pragma unroll
                for (int ntp = 0; ntp < 4; ntp++) {
                    mma16816(c[mt][ntp * 2],     a[mt], &b[ntp][0]);
                    mma16816(c[mt][ntp * 2 + 1], a[mt], &b[ntp][2]);
                }
        }
    }

#pragma unroll
    for (int mt = 0; mt < 2; mt++) {
#pragma unroll
        for (int nt = 0; nt < 8; nt++) {
            int col = wn + nt * 8 + qc;
            float b0 = bias[col], b1 = bias[col + 1];
            int r0 = n0 + wm + mt * 16 + qr;
            size_t g0 = (size_t)r0 * ostride + ocol0 + col;
            size_t g1 = (size_t)(r0 + 8) * ostride + ocol0 + col;
            *(float2*)&out[g0] = make_float2(c[mt][nt][0] + b0, c[mt][nt][1] + b1);
            *(float2*)&out[g1] = make_float2(c[mt][nt][2] + b0, c[mt][nt][3] + b1);
        }
    }
}

// pair driver: load B + A(t0) [group1], A(t1) [group0-overlapped], compute both.
__device__ __forceinline__ void gemm_pair(
    const __nv_bfloat16* __restrict__ Ah, const __nv_bfloat16* __restrict__ Al,
    int brow0, const float* __restrict__ bias, float* __restrict__ out,
    int ostride, int ocol0, int t0, __nv_bfloat16* smem)
{
    __nv_bfloat16* sB  = smem;
    __nv_bfloat16* sA0 = smem + 128 * AS_STR;
    __nv_bfloat16* sA1 = smem + 2 * 128 * AS_STR;
    const int tid = threadIdx.x;
    const int t1 = t0 + 1;
    const bool has2 = (t1 < NT);

    issue_tile(g_wh, g_wl, brow0, smem_u32(sB), tid);
    issue_tile(Ah, Al, t0 * 128, smem_u32(sA0), tid);
    CPA_COMMIT();
    if (has2) {
        issue_tile(Ah, Al, t1 * 128, smem_u32(sA1), tid);
        CPA_COMMIT();
        CPA_WAIT1();
    } else {
        CPA_WAIT0();
    }
    __syncthreads();

    gemm_tile(sA0, sB, bias, out, ostride, ocol0, t0 * 128);

    if (has2) {
        CPA_WAIT0();
        __syncthreads();
        gemm_tile(sA1, sB, bias, out, ostride, ocol0, t1 * 128);
    }
}

__global__ __launch_bounds__(256) void gemm_main_kernel(
    const float* __restrict__ b_ih, const float* __restrict__ b_hh)
{
    extern __shared__ __align__(16) __nv_bfloat16 smem[];
    const int bx = blockIdx.x;
    const bool ih = (bx < 3);
    gemm_pair(ih ? g_agh : g_xh, ih ? g_agl : g_xl,
              bx * 128,
              ih ? (b_ih + bx * 128) : (b_hh + (bx - 3) * 128),
              g_g, 768, bx * 128, blockIdx.y * 2, smem);
}

__global__ __launch_bounds__(256) void gemm_msg_kernel(const float* __restrict__ b_msg)
{
    extern __shared__ __align__(16) __nv_bfloat16 smem[];
    gemm_pair(g_xh, g_xl, 768, b_msg, g_m, 128, 0, blockIdx.x * 2, smem);
}

// =================================================================================
// Kernel D: GRU elementwise + BN column-stat accumulation.
// =================================================================================
__global__ __launch_bounds__(256) void gru_kernel(const float* __restrict__ x)
{
    __shared__ float rs_[8][128];
    __shared__ float rq_[8][128];

    const int tid = threadIdx.x;
    const int c4 = tid & 31;
    const int rs = tid >> 5;
    float4 s = make_float4(0.f, 0.f, 0.f, 0.f);
    float4 q = make_float4(0.f, 0.f, 0.f, 0.f);

    for (int it = 0; it < 16; it++) {
        int n = blockIdx.x * 128 + it * 8 + rs;
        if (n >= N_NODES) break;
        size_t gb = (size_t)n * 768 + c4 * 4;
        float4 ir = *(const float4*)&g_g[gb];
        float4 iz = *(const float4*)&g_g[gb + 128];
        float4 in_ = *(const float4*)&g_g[gb + 256];
        float4 hr = *(const float4*)&g_g[gb + 384];
        float4 hz = *(const float4*)&g_g[gb + 512];
        float4 hn = *(const float4*)&g_g[gb + 640];
        float4 xv = *(const float4*)&x[(size_t)n * D + c4 * 4];

        float4 h;
        {
            float r = sigm(ir.x + hr.x), z = sigm(iz.x + hz.x);
            float nn = tanhf(in_.x + r * hn.x); h.x = (1.f - z) * nn + z * xv.x;
        }
        {
            float r = sigm(ir.y + hr.y), z = sigm(iz.y + hz.y);
            float nn = tanhf(in_.y + r * hn.y); h.y = (1.f - z) * nn + z * xv.y;
        }
        {
            float r = sigm(ir.z + hr.z), z = sigm(iz.z + hz.z);
            float nn = tanhf(in_.z + r * hn.z); h.z = (1.f - z) * nn + z * xv.z;
        }
        {
            float r = sigm(ir.w + hr.w), z = sigm(iz.w + hz.w);
            float nn = tanhf(in_.w + r * hn.w); h.w = (1.f - z) * nn + z * xv.w;
        }
        *(float4*)&g_h[(size_t)n * D + c4 * 4] = h;
        s.x += h.x; s.y += h.y; s.z += h.z; s.w += h.w;
        q.x += h.x * h.x; q.y += h.y * h.y; q.z += h.z * h.z; q.w += h.w * h.w;
    }

    *(float4*)&rs_[rs][c4 * 4] = s;
    *(float4*)&rq_[rs][c4 * 4] = q;
    __syncthreads();
    if (tid < 128) {
        float a = 0.f, b = 0.f;
#pragma unroll
        for (int r = 0; r < 8; r++) { a += rs_[r][tid]; b += rq_[r][tid]; }
        atomicAdd(&g_sum[tid], a);
        atomicAdd(&g_ssq[tid], b);
    }
}

// =================================================================================
// Kernel E: BatchNorm normalize.
// =================================================================================
__global__ __launch_bounds__(256) void bn_kernel(
    const float* __restrict__ gamma, const float* __restrict__ beta,
    float* __restrict__ out)
{
    int idx = blockIdx.x * 256 + threadIdx.x;
    if (idx >= N_NODES * 32) return;
    int c4 = idx & 31;
    const float inv_n = 1.f / (float)N_NODES;

    float4 h  = *(const float4*)&g_h[(size_t)idx * 4];
    float4 sm = *(const float4*)&g_sum[c4 * 4];
    float4 sq = *(const float4*)&g_ssq[c4 * 4];
    float4 ga = *(const float4*)&gamma[c4 * 4];
    float4 be = *(const float4*)&beta[c4 * 4];

    float4 o;
    {
        float mean = sm.x * inv_n; float var = sq.x * inv_n - mean * mean;
        o.x = ga.x * (h.x - mean) * rsqrtf(var + BN_EPS) + be.x;
    }
    {
        float mean = sm.y * inv_n; float var = sq.y * inv_n - mean * mean;
        o.y = ga.y * (h.y - mean) * rsqrtf(var + BN_EPS) + be.y;
    }
    {
        float mean = sm.z * inv_n; float var = sq.z * inv_n - mean * mean;
        o.z = ga.z * (h.z - mean) * rsqrtf(var + BN_EPS) + be.z;
    }
    {
        float mean = sm.w * inv_n; float var = sq.w * inv_n - mean * mean;
        o.w = ga.w * (h.w - mean) * rsqrtf(var + BN_EPS) + be.w;
    }
    *(float4*)&out[(size_t)idx * 4] = o;
}

// =================================================================================
extern "C" void kernel_launch(void* const* d_in, const int* in_sizes, int n_in,
                              void* d_out, int out_size)
{
    const float* x     = (const float*)d_in[0];
    const void*  ei    = d_in[1];
    const float* W_msg = (const float*)d_in[2];
    const float* b_msg = (const float*)d_in[3];
    const float* W_att = (const float*)d_in[4];
    const float* b_att = (const float*)d_in[5];
    const float* W_ih  = (const float*)d_in[6];
    const float* b_ih  = (const float*)d_in[7];
    const float* W_hh  = (const float*)d_in[8];
    const float* b_hh  = (const float*)d_in[9];
    const float* gamma = (const float*)d_in[10];
    const float* beta  = (const float*)d_in[11];
    float* out = (float*)d_out;

    const int E = in_sizes[1] / 2;
    const int PAIRS = (NT + 1) / 2;   // 196

    static int smem_set = 0;
    if (!smem_set) {
        cudaFuncSetAttribute(gemm_main_kernel,
                             cudaFuncAttributeMaxDynamicSharedMemorySize, SMEM_GEMM);
        cudaFuncSetAttribute(gemm_msg_kernel,
                             cudaFuncAttributeMaxDynamicSharedMemorySize, SMEM_GEMM);
        smem_set = 1;
    }

    detect_kernel<<<1, 1>>>(ei, E);
    node_pre_kernel<<<NP / 64, 256>>>(x, W_att);
    convert_w_kernel<<<(CVT_W_Q + 255) / 256, 256>>>(W_ih, W_hh, W_msg);
    gemm_msg_kernel<<<PAIRS, 256, SMEM_GEMM>>>(b_msg);
    hist_kernel<<<(E + 255) / 256, 256>>>(ei, E);
    scan_a_kernel<<<NSCAN / 256, 256>>>();
    scan_b_kernel<<<1, 256>>>();
    scan_c_kernel<<<NSCAN / 256, 256>>>();
    scatter_kernel<<<(E + 255) / 256, 256>>>(ei, E);
    gather_kernel<<<(NP + 7) / 8, 256>>>(b_att);
    gemm_main_kernel<<<dim3(6, PAIRS), 256, SMEM_GEMM>>>(b_ih, b_hh);
    gru_kernel<<<NP / 128, 256>>>(x);
    bn_kernel<<<(N_NODES * 32 + 255) / 256, 256>>>(gamma, beta, out);
}

// round 10
// speedup vs baseline: 1.3667x; 1.0013x over previous
#include <cuda_runtime.h>
#include <cuda_bf16.h>
#include <cstdint>
#include <cstddef>

// Problem constants
#define N_NODES 50000
#define NP      50048          // padded: 782*64 = 391*128
#define NSCAN   50176          // NP + 128, = 196*256 for scan
#define NT      391            // node tiles of 128
#define D       128
#define E_MAX   800000
#define BN_EPS  1e-5f

// ---------------- scratch (static device globals; no runtime alloc) -------------
__device__ float g_x  [(size_t)NP * D];
__device__ float g_m  [(size_t)NP * D];
__device__ float g_as [NP];
__device__ float g_ad [NP];
__device__ float g_g  [(size_t)NP * 768];
__device__ float g_h  [(size_t)NP * D];
__device__ float g_sum[D];
__device__ float g_ssq[D];
__device__ int   g_is64;

// CSR build for edge gather
__device__ int g_cnt [NSCAN];
__device__ int g_off [NSCAN];
__device__ int g_bsum[256];
__device__ int g_boff[256];
__device__ int g_start[NSCAN];
__device__ int g_cur [NSCAN];
__device__ int g_esrc[E_MAX];

// bf16 hi/lo planes for tensor-core GEMMs
__device__ __nv_bfloat16 g_xh  [(size_t)NP * D];
__device__ __nv_bfloat16 g_xl  [(size_t)NP * D];
__device__ __nv_bfloat16 g_agh [(size_t)NP * D];
__device__ __nv_bfloat16 g_agl [(size_t)NP * D];
__device__ __nv_bfloat16 g_wh  [896 * D];   // [W_ih(384); W_hh(384); W_msg^T(128)] hi
__device__ __nv_bfloat16 g_wl  [896 * D];   // lo

__device__ __forceinline__ float sigm(float v) { return 1.f / (1.f + __expf(-v)); }

__device__ __forceinline__ uint32_t smem_u32(const void* p) {
    uint32_t a;
    asm("{ .reg .u64 t; cvta.to.shared.u64 t, %1; cvt.u32.u64 %0, t; }" : "=r"(a) : "l"(p));
    return a;
}
__device__ __forceinline__ void f2bf(float v, __nv_bfloat16& h, __nv_bfloat16& l) {
    h = __float2bfloat16(v);
    l = __float2bfloat16(v - __bfloat162float(h));
}
__device__ __forceinline__ void cpa16(uint32_t dst, const void* src) {
    asm volatile("cp.async.ca.shared.global [%0], [%1], 16;" :: "r"(dst), "l"(src));
}
#define CPA_COMMIT() asm volatile("cp.async.commit_group;" ::: "memory")
#define CPA_WAIT0()  asm volatile("cp.async.wait_group 0;" ::: "memory")
#define CPA_WAIT1()  asm volatile("cp.async.wait_group 1;" ::: "memory")

// =================================================================================
// Kernel 0: detect edge_index dtype (int32 vs int64).
// =================================================================================
__global__ void detect_kernel(const void* ei_raw, int E)
{
    const long long* e64 = (const long long*)ei_raw;
    int n = E < 64 ? E : 64;
    int ok = 1;
    for (int i = 0; i < n; i++) {
        long long v = e64[i];
        if (v < 0 || v >= N_NODES) { ok = 0; break; }
    }
    g_is64 = ok;
}

__device__ __forceinline__ void load_edge(const void* ei_raw, int E, int e,
                                          int& src, int& dst)
{
    if (g_is64) {
        const long long* p = (const long long*)ei_raw;
        src = (int)p[e];
        dst = (int)p[(size_t)E + e];
    } else {
        const int* p = (const int*)ei_raw;
        src = p[e];
        dst = p[E + e];
    }
}

// =================================================================================
// Kernel A: x copy + bf16 planes + attention pre-dots + zeroing.
// =================================================================================
__global__ __launch_bounds__(256) void node_pre_kernel(
    const float* __restrict__ x, const float* __restrict__ W_att)
{
    __shared__ __align__(16) float xs[64][132];
    __shared__ float Was[128], Wad[128];

    const int tid = threadIdx.x;
    const int n0  = blockIdx.x * 64;

    if (tid < 128) { Was[tid] = W_att[tid]; Wad[tid] = W_att[128 + tid]; }
    if (tid < 64) g_cnt[n0 + tid] = 0;
    if (blockIdx.x == 0 && tid < 128) {
        g_sum[tid] = 0.f; g_ssq[tid] = 0.f; g_cnt[NP + tid] = 0;
    }

    for (int i = tid; i < 64 * 32; i += 256) {
        int node = i >> 5, cq = i & 31;
        float4 v = make_float4(0.f, 0.f, 0.f, 0.f);
        int gn = n0 + node;
        if (gn < N_NODES) v = *(const float4*)&x[(size_t)gn * D + cq * 4];
        *(float4*)&xs[node][cq * 4] = v;
        *(float4*)&g_x[(size_t)gn * D + cq * 4] = v;
        __nv_bfloat162 h01, h23, l01, l23;
        f2bf(v.x, h01.x, l01.x); f2bf(v.y, h01.y, l01.y);
        f2bf(v.z, h23.x, l23.x); f2bf(v.w, h23.y, l23.y);
        *(__nv_bfloat162*)&g_xh[(size_t)gn * D + cq * 4]     = h01;
        *(__nv_bfloat162*)&g_xh[(size_t)gn * D + cq * 4 + 2] = h23;
        *(__nv_bfloat162*)&g_xl[(size_t)gn * D + cq * 4]     = l01;
        *(__nv_bfloat162*)&g_xl[(size_t)gn * D + cq * 4 + 2] = l23;
    }
    __syncthreads();

    if (tid < 128) {
        int node = tid >> 1, sel = tid & 1;
        const float* wv = sel ? Wad : Was;
        float a0 = 0.f, a1 = 0.f, a2 = 0.f, a3 = 0.f;
#pragma unroll 8
        for (int k = 0; k < 128; k += 4) {
            a0 += xs[node][k]     * wv[k];
            a1 += xs[node][k + 1] * wv[k + 1];
            a2 += xs[node][k + 2] * wv[k + 2];
            a3 += xs[node][k + 3] * wv[k + 3];
        }
        float r = (a0 + a1) + (a2 + a3);
        if (sel) g_ad[n0 + node] = r; else g_as[n0 + node] = r;
    }
}

// =================================================================================
// Convert weights -> stacked bf16 hi/lo planes.
// Rows 0..383: W_ih; 384..767: W_hh; 768..895: W_msg^T.
// =================================================================================
#define CVT_W_Q (896 * 32)
__global__ __launch_bounds__(256) void convert_w_kernel(
    const float* __restrict__ W_ih, const float* __restrict__ W_hh,
    const float* __restrict__ W_msg)
{
    int idx = blockIdx.x * 256 + threadIdx.x;
    if (idx >= CVT_W_Q) return;
    int row = idx >> 5, cq = idx & 31;
    size_t off = (size_t)row * D + cq * 4;

    float4 v;
    if (row < 384) {
        v = *(const float4*)&W_ih[(size_t)row * D + cq * 4];
    } else if (row < 768) {
        v = *(const float4*)&W_hh[(size_t)(row - 384) * D + cq * 4];
    } else {
        int j = row - 768;
        int k = cq * 4;
        v.x = W_msg[(size_t)(k + 0) * D + j];
        v.y = W_msg[(size_t)(k + 1) * D + j];
        v.z = W_msg[(size_t)(k + 2) * D + j];
        v.w = W_msg[(size_t)(k + 3) * D + j];
    }
    __nv_bfloat162 h01, h23, l01, l23;
    f2bf(v.x, h01.x, l01.x); f2bf(v.y, h01.y, l01.y);
    f2bf(v.z, h23.x, l23.x); f2bf(v.w, h23.y, l23.y);
    *(__nv_bfloat162*)&g_wh[off]     = h01;
    *(__nv_bfloat162*)&g_wh[off + 2] = h23;
    *(__nv_bfloat162*)&g_wl[off]     = l01;
    *(__nv_bfloat162*)&g_wl[off + 2] = l23;
}

// =================================================================================
// CSR build: histogram -> scan (3 kernels) -> scatter.
// =================================================================================
__global__ __launch_bounds__(256) void hist_kernel(const void* __restrict__ ei, int E)
{
    int e = blockIdx.x * 256 + threadIdx.x;
    if (e >= E) return;
    int src, dst;
    load_edge(ei, E, e, src, dst);
    if ((unsigned)dst >= N_NODES) return;
    atomicAdd(&g_cnt[dst], 1);
}

__global__ __launch_bounds__(256) void scan_a_kernel()
{
    __shared__ int sh[256];
    const int tid = threadIdx.x;
    int t = blockIdx.x * 256 + tid;
    int v = g_cnt[t];
    sh[tid] = v; __syncthreads();
#pragma unroll
    for (int o = 1; o < 256; o <<= 1) {
        int u = (tid >= o) ? sh[tid - o] : 0;
        __syncthreads();
        sh[tid] += u;
        __syncthreads();
    }
    g_off[t] = sh[tid] - v;
    if (tid == 255) g_bsum[blockIdx.x] = sh[255];
}

__global__ __launch_bounds__(256) void scan_b_kernel()
{
    __shared__ int sh[256];
    const int tid = threadIdx.x;
    int v = (tid < NSCAN / 256) ? g_bsum[tid] : 0;
    sh[tid] = v; __syncthreads();
#pragma unroll
    for (int o = 1; o < 256; o <<= 1) {
        int u = (tid >= o) ? sh[tid - o] : 0;
        __syncthreads();
        sh[tid] += u;
        __syncthreads();
    }
    g_boff[tid] = sh[tid] - v;
}

__global__ __launch_bounds__(256) void scan_c_kernel()
{
    int t = blockIdx.x * 256 + threadIdx.x;
    int s = g_off[t] + g_boff[blockIdx.x];
    g_start[t] = s;
    g_cur[t]   = s;
}

__global__ __launch_bounds__(256) void scatter_kernel(const void* __restrict__ ei, int E)
{
    int e = blockIdx.x * 256 + threadIdx.x;
    if (e >= E) return;
    int src, dst;
    load_edge(ei, E, e, src, dst);
    if ((unsigned)src >= N_NODES || (unsigned)dst >= N_NODES) return;
    int p = atomicAdd(&g_cur[dst], 1);
    if (p < E) g_esrc[p] = src;
}

// =================================================================================
// Gather: one warp per dst node; writes agg directly as bf16 hi/lo planes.
// =================================================================================
__global__ __launch_bounds__(256) void gather_kernel(const float* __restrict__ b_att)
{
    const int wid  = threadIdx.x >> 5;
    const int lane = threadIdx.x & 31;
    const int n = blockIdx.x * 8 + wid;
    if (n >= NP) return;

    const int s0 = g_start[n];
    const int s1 = g_start[n + 1];
    const float adb = ((n < N_NODES) ? g_ad[n] : 0.f) + b_att[0];

    float4 acc = make_float4(0.f, 0.f, 0.f, 0.f);
    int i = s0;
    for (; i + 1 < s1; i += 2) {
        int src0 = g_esrc[i], src1 = g_esrc[i + 1];
        float at0 = sigm(g_as[src0] + adb);
        float at1 = sigm(g_as[src1] + adb);
        float4 v0 = *(const float4*)&g_m[(size_t)src0 * D + lane * 4];
        float4 v1 = *(const float4*)&g_m[(size_t)src1 * D + lane * 4];
        acc.x += v0.x * at0 + v1.x * at1;
        acc.y += v0.y * at0 + v1.y * at1;
        acc.z += v0.z * at0 + v1.z * at1;
        acc.w += v0.w * at0 + v1.w * at1;
    }
    if (i < s1) {
        int src0 = g_esrc[i];
        float at0 = sigm(g_as[src0] + adb);
        float4 v0 = *(const float4*)&g_m[(size_t)src0 * D + lane * 4];
        acc.x += v0.x * at0; acc.y += v0.y * at0;
        acc.z += v0.z * at0; acc.w += v0.w * at0;
    }
    __nv_bfloat162 h01, h23, l01, l23;
    f2bf(acc.x, h01.x, l01.x); f2bf(acc.y, h01.y, l01.y);
    f2bf(acc.z, h23.x, l23.x); f2bf(acc.w, h23.y, l23.y);
    size_t o = (size_t)n * D + lane * 4;
    *(__nv_bfloat162*)&g_agh[o]     = h01;
    *(__nv_bfloat162*)&g_agh[o + 2] = h23;
    *(__nv_bfloat162*)&g_agl[o]     = l01;
    *(__nv_bfloat162*)&g_agl[o + 2] = l23;
}

// =================================================================================
// Split-bf16 GEMM, pair-tile version with __noinline__ tile body so accumulators
// and pipeline temps cannot live across the prefetch machinery (R8/R9 had
// regs=255 + spills from cross-tile scheduling after inlining).
// =================================================================================
#define AS_STR 264
#define SMEM_GEMM (3 * 128 * AS_STR * 2)

__device__ __forceinline__ void mma16816(float* c, const uint32_t* a, const uint32_t* b) {
    asm volatile(
        "mma.sync.aligned.m16n8k16.row.col.f32.bf16.bf16.f32 "
        "{%0,%1,%2,%3}, {%4,%5,%6,%7}, {%8,%9}, {%0,%1,%2,%3};"
        : "+f"(c[0]), "+f"(c[1]), "+f"(c[2]), "+f"(c[3])
        : "r"(a[0]), "r"(a[1]), "r"(a[2]), "r"(a[3]), "r"(b[0]), "r"(b[1]));
}
__device__ __forceinline__ void ldmx4(uint32_t* d, uint32_t addr) {
    asm volatile("ldmatrix.sync.aligned.m8n8.x4.shared.b16 {%0,%1,%2,%3}, [%4];"
                 : "=r"(d[0]), "=r"(d[1]), "=r"(d[2]), "=r"(d[3]) : "r"(addr));
}

// async-load one 128-row tile (hi+lo planes) into smem at byte address s_b
__device__ __forceinline__ void issue_tile(
    const __nv_bfloat16* __restrict__ Ph, const __nv_bfloat16* __restrict__ Pl,
    int row0, uint32_t s_b, int tid)
{
#pragma unroll
    for (int it = 0; it < 8; it++) {
        int i = tid + it * 256;
        int row = i >> 4, col = (i & 15) * 8;
        uint32_t d = s_b + (uint32_t)(row * AS_STR + col) * 2;
        size_t gs = (size_t)(row0 + row) * D + col;
        cpa16(d, &Ph[gs]);
        cpa16(d + 256, &Pl[gs]);
    }
}

// compute one 128x128 tile from sA and sB. __noinline__: hard register barrier.
__device__ __noinline__ void gemm_tile(
    const __nv_bfloat16* sA, const __nv_bfloat16* sB,
    const float* __restrict__ bias, float* __restrict__ out,
    int ostride, int ocol0, int n0)
{
    const int tid  = threadIdx.x;
    const int wid  = tid >> 5;
    const int lane = tid & 31;
    const int wm = (wid & 3) * 32;
    const int wn = (wid >> 2) * 64;
    const int g  = lane >> 3;
    const int r  = lane & 7;
    const int qr = lane >> 2;
    const int qc = (lane & 3) * 2;

    uint32_t aBase[2], bBase[4];
#pragma unroll
    for (int mt = 0; mt < 2; mt++) {
        int row = wm + mt * 16 + ((g & 1) ? 8 : 0) + r;
        int col = (g >= 2) ? 8 : 0;
        aBase[mt] = smem_u32(&sA[row * AS_STR + col]);
    }
#pragma unroll
    for (int ntp = 0; ntp < 4; ntp++) {
        int row = wn + (ntp * 2 + (g >> 1)) * 8 + r;
        int col = (g & 1) ? 8 : 0;
        bBase[ntp] = smem_u32(&sB[row * AS_STR + col]);
    }

    float c[2][8][4];
#pragma unroll
    for (int mt = 0; mt < 2; mt++)
#pragma unroll
        for (int nt = 0; nt < 8; nt++)
#pragma unroll
            for (int j = 0; j < 4; j++) c[mt][nt][j] = 0.f;

#pragma unroll
    for (int pass = 0; pass < 3; pass++) {
        const int kA = (pass == 1) ? 128 : 0;
        const int kB = (pass == 2) ? 128 : 0;
#pragma unroll
        for (int s = 0; s < 8; s++) {
            const uint32_t offA = (uint32_t)((kA + s * 16) * 2);
            const uint32_t offB = (uint32_t)((kB + s * 16) * 2);
            uint32_t a[2][4], b[4][4];
            ldmx4(a[0], aBase[0] + offA);
            ldmx4(a[1], aBase[1] + offA);
#pragma unroll
            for (int ntp = 0; ntp < 4; ntp++) ldmx4(b[ntp], bBase[ntp] + offB);
#pragma unroll
            for (int mt = 0; mt < 2; mt++)
#pragma unroll
                for (int ntp = 0; ntp < 4; ntp++) {
                    mma16816(c[mt][ntp * 2],     a[mt], &b[ntp][0]);
                    mma16816(c[mt][ntp * 2 + 1], a[mt], &b[ntp][2]);
                }
        }
    }

#pragma unroll
    for (int mt = 0; mt < 2; mt++) {
#pragma unroll
        for (int nt = 0; nt < 8; nt++) {
            int col = wn + nt * 8 + qc;
            float b0 = bias[col], b1 = bias[col + 1];
            int r0 = n0 + wm + mt * 16 + qr;
            size_t g0 = (size_t)r0 * ostride + ocol0 + col;
            size_t g1 = (size_t)(r0 + 8) * ostride + ocol0 + col;
            *(float2*)&out[g0] = make_float2(c[mt][nt][0] + b0, c[mt][nt][1] + b1);
            *(float2*)&out[g1] = make_float2(c[mt][nt][2] + b0, c[mt][nt][3] + b1);
        }
    }
}

// pair driver: load B + A(t0), A(t1) overlapped with tile0 compute.
__device__ __forceinline__ void gemm_pair(
    const __nv_bfloat16* __restrict__ Ah, const __nv_bfloat16* __restrict__ Al,
    int brow0, const float* __restrict__ bias, float* __restrict__ out,
    int ostride, int ocol0, int t0, __nv_bfloat16* smem)
{
    __nv_bfloat16* sB  = smem;
    __nv_bfloat16* sA0 = smem + 128 * AS_STR;
    __nv_bfloat16* sA1 = smem + 2 * 128 * AS_STR;
    const int tid = threadIdx.x;
    const int t1 = t0 + 1;
    const bool has2 = (t1 < NT);

    issue_tile(g_wh, g_wl, brow0, smem_u32(sB), tid);
    issue_tile(Ah, Al, t0 * 128, smem_u32(sA0), tid);
    CPA_COMMIT();
    if (has2) {
        issue_tile(Ah, Al, t1 * 128, smem_u32(sA1), tid);
        CPA_COMMIT();
        CPA_WAIT1();
    } else {
        CPA_WAIT0();
    }
    __syncthreads();

    gemm_tile(sA0, sB, bias, out, ostride, ocol0, t0 * 128);

    if (has2) {
        CPA_WAIT0();
        __syncthreads();
        gemm_tile(sA1, sB, bias, out, ostride, ocol0, t1 * 128);
    }
}

__global__ __launch_bounds__(256) void gemm_main_kernel(
    const float* __restrict__ b_ih, const float* __restrict__ b_hh)
{
    extern __shared__ __align__(16) __nv_bfloat16 smem[];
    const int bx = blockIdx.x;
    const bool ih = (bx < 3);
    gemm_pair(ih ? g_agh : g_xh, ih ? g_agl : g_xl,
              bx * 128,
              ih ? (b_ih + bx * 128) : (b_hh + (bx - 3) * 128),
              g_g, 768, bx * 128, blockIdx.y * 2, smem);
}

__global__ __launch_bounds__(256) void gemm_msg_kernel(const float* __restrict__ b_msg)
{
    extern __shared__ __align__(16) __nv_bfloat16 smem[];
    gemm_pair(g_xh, g_xl, 768, b_msg, g_m, 128, 0, blockIdx.x * 2, smem);
}

// =================================================================================
// Kernel D: GRU elementwise + BN column-stat accumulation.
// =================================================================================
__global__ __launch_bounds__(256) void gru_kernel(const float* __restrict__ x)
{
    __shared__ float rs_[8][128];
    __shared__ float rq_[8][128];

    const int tid = threadIdx.x;
    const int c4 = tid & 31;
    const int rs = tid >> 5;
    float4 s = make_float4(0.f, 0.f, 0.f, 0.f);
    float4 q = make_float4(0.f, 0.f, 0.f, 0.f);

    for (int it = 0; it < 16; it++) {
        int n = blockIdx.x * 128 + it * 8 + rs;
        if (n >= N_NODES) break;
        size_t gb = (size_t)n * 768 + c4 * 4;
        float4 ir = *(const float4*)&g_g[gb];
        float4 iz = *(const float4*)&g_g[gb + 128];
        float4 in_ = *(const float4*)&g_g[gb + 256];
        float4 hr = *(const float4*)&g_g[gb + 384];
        float4 hz = *(const float4*)&g_g[gb + 512];
        float4 hn = *(const float4*)&g_g[gb + 640];
        float4 xv = *(const float4*)&x[(size_t)n * D + c4 * 4];

        float4 h;
        {
            float r = sigm(ir.x + hr.x), z = sigm(iz.x + hz.x);
            float nn = tanhf(in_.x + r * hn.x); h.x = (1.f - z) * nn + z * xv.x;
        }
        {
            float r = sigm(ir.y + hr.y), z = sigm(iz.y + hz.y);
            float nn = tanhf(in_.y + r * hn.y); h.y = (1.f - z) * nn + z * xv.y;
        }
        {
            float r = sigm(ir.z + hr.z), z = sigm(iz.z + hz.z);
            float nn = tanhf(in_.z + r * hn.z); h.z = (1.f - z) * nn + z * xv.z;
        }
        {
            float r = sigm(ir.w + hr.w), z = sigm(iz.w + hz.w);
            float nn = tanhf(in_.w + r * hn.w); h.w = (1.f - z) * nn + z * xv.w;
        }
        *(float4*)&g_h[(size_t)n * D + c4 * 4] = h;
        s.x += h.x; s.y += h.y; s.z += h.z; s.w += h.w;
        q.x += h.x * h.x; q.y += h.y * h.y; q.z += h.z * h.z; q.w += h.w * h.w;
    }

    *(float4*)&rs_[rs][c4 * 4] = s;
    *(float4*)&rq_[rs][c4 * 4] = q;
    __syncthreads();
    if (tid < 128) {
        float a = 0.f, b = 0.f;
#pragma unroll
        for (int r = 0; r < 8; r++) { a += rs_[r][tid]; b += rq_[r][tid]; }
        atomicAdd(&g_sum[tid], a);
        atomicAdd(&g_ssq[tid], b);
    }
}

// =================================================================================
// Kernel E: BatchNorm normalize.
// =================================================================================
__global__ __launch_bounds__(256) void bn_kernel(
    const float* __restrict__ gamma, const float* __restrict__ beta,
    float* __restrict__ out)
{
    int idx = blockIdx.x * 256 + threadIdx.x;
    if (idx >= N_NODES * 32) return;
    int c4 = idx & 31;
    const float inv_n = 1.f / (float)N_NODES;

    float4 h  = *(const float4*)&g_h[(size_t)idx * 4];
    float4 sm = *(const float4*)&g_sum[c4 * 4];
    float4 sq = *(const float4*)&g_ssq[c4 * 4];
    float4 ga = *(const float4*)&gamma[c4 * 4];
    float4 be = *(const float4*)&beta[c4 * 4];

    float4 o;
    {
        float mean = sm.x * inv_n; float var = sq.x * inv_n - mean * mean;
        o.x = ga.x * (h.x - mean) * rsqrtf(var + BN_EPS) + be.x;
    }
    {
        float mean = sm.y * inv_n; float var = sq.y * inv_n - mean * mean;
        o.y = ga.y * (h.y - mean) * rsqrtf(var + BN_EPS) + be.y;
    }
    {
        float mean = sm.z * inv_n; float var = sq.z * inv_n - mean * mean;
        o.z = ga.z * (h.z - mean) * rsqrtf(var + BN_EPS) + be.z;
    }
    {
        float mean = sm.w * inv_n; float var = sq.w * inv_n - mean * mean;
        o.w = ga.w * (h.w - mean) * rsqrtf(var + BN_EPS) + be.w;
    }
    *(float4*)&out[(size_t)idx * 4] = o;
}

// =================================================================================
extern "C" void kernel_launch(void* const* d_in, const int* in_sizes, int n_in,
                              void* d_out, int out_size)
{
    const float* x     = (const float*)d_in[0];
    const void*  ei    = d_in[1];
    const float* W_msg = (const float*)d_in[2];
    const float* b_msg = (const float*)d_in[3];
    const float* W_att = (const float*)d_in[4];
    const float* b_att = (const float*)d_in[5];
    const float* W_ih  = (const float*)d_in[6];
    const float* b_ih  = (const float*)d_in[7];
    const float* W_hh  = (const float*)d_in[8];
    const float* b_hh  = (const float*)d_in[9];
    const float* gamma = (const float*)d_in[10];
    const float* beta  = (const float*)d_in[11];
    float* out = (float*)d_out;

    const int E = in_sizes[1] / 2;
    const int PAIRS = (NT + 1) / 2;   // 196

    static int smem_set = 0;
    if (!smem_set) {
        cudaFuncSetAttribute(gemm_main_kernel,
                             cudaFuncAttributeMaxDynamicSharedMemorySize, SMEM_GEMM);
        cudaFuncSetAttribute(gemm_msg_kernel,
                             cudaFuncAttributeMaxDynamicSharedMemorySize, SMEM_GEMM);
        smem_set = 1;
    }

    detect_kernel<<<1, 1>>>(ei, E);
    node_pre_kernel<<<NP / 64, 256>>>(x, W_att);
    convert_w_kernel<<<(CVT_W_Q + 255) / 256, 256>>>(W_ih, W_hh, W_msg);
    gemm_msg_kernel<<<PAIRS, 256, SMEM_GEMM>>>(b_msg);
    hist_kernel<<<(E + 255) / 256, 256>>>(ei, E);
    scan_a_kernel<<<NSCAN / 256, 256>>>();
    scan_b_kernel<<<1, 256>>>();
    scan_c_kernel<<<NSCAN / 256, 256>>>();
    scatter_kernel<<<(E + 255) / 256, 256>>>(ei, E);
    gather_kernel<<<(NP + 7) / 8, 256>>>(b_att);
    gemm_main_kernel<<<dim3(6, PAIRS), 256, SMEM_GEMM>>>(b_ih, b_hh);
    gru_kernel<<<NP / 128, 256>>>(x);
    bn_kernel<<<(N_NODES * 32 + 255) / 256, 256>>>(gamma, beta, out);
}

// round 12
// speedup vs baseline: 1.4989x; 1.0967x over previous
#include <cuda_runtime.h>
#include <cuda_bf16.h>
#include <cstdint>
#include <cstddef>

// Problem constants
#define N_NODES 50000
#define NP      50048          // padded: 782*64 = 391*128
#define NSCAN   50176          // NP + 128, = 196*256 for scan
#define NT      391            // node tiles of 128
#define D       128
#define E_MAX   800000
#define BN_EPS  1e-5f
#define ROWB    264            // bf16 per packed row: [hi 128 | lo 128 | pad 8]

// ---------------- scratch (static device globals; no runtime alloc) -------------
__device__ float g_m  [(size_t)NP * D];
__device__ float g_as [NP];
__device__ float g_ad [NP];
__device__ float g_g  [(size_t)NP * 768];
__device__ float g_h  [(size_t)NP * D];
__device__ float g_sum[D];
__device__ float g_ssq[D];
__device__ int   g_is64;

// CSR build for edge gather
__device__ int g_cnt [NSCAN];
__device__ int g_off [NSCAN];
__device__ int g_bsum[256];
__device__ int g_boff[256];
__device__ int g_start[NSCAN];
__device__ int g_cur [NSCAN];
__device__ int g_esrc[E_MAX];

// packed bf16 hi|lo planes (row stride ROWB, smem-identical layout for bulk copy)
__device__ __align__(128) __nv_bfloat16 g_xP [(size_t)NP * ROWB];
__device__ __align__(128) __nv_bfloat16 g_agP[(size_t)NP * ROWB];
__device__ __align__(128) __nv_bfloat16 g_wP [896 * ROWB];  // [W_ih(384);W_hh(384);W_msg^T(128)]

__device__ __forceinline__ float sigm(float v) { return 1.f / (1.f + __expf(-v)); }

__device__ __forceinline__ uint32_t smem_u32(const void* p) {
    uint32_t a;
    asm("{ .reg .u64 t; cvta.to.shared.u64 t, %1; cvt.u32.u64 %0, t; }" : "=r"(a) : "l"(p));
    return a;
}
__device__ __forceinline__ void f2bf(float v, __nv_bfloat16& h, __nv_bfloat16& l) {
    h = __float2bfloat16(v);
    l = __float2bfloat16(v - __bfloat162float(h));
}

#define MBAR_INIT(mb, c) asm volatile("mbarrier.init.shared.b64 [%0], %1;" :: "r"(mb), "r"(c) : "memory")
#define MBAR_EXPECT_TX(mb, n) asm volatile("mbarrier.arrive.expect_tx.shared.b64 _, [%0], %1;" :: "r"(mb), "r"(n) : "memory")
__device__ __forceinline__ void bulk_ld(uint32_t dst, const void* src, uint32_t bytes, uint32_t mbar) {
    asm volatile(
        "cp.async.bulk.shared::cta.global.mbarrier::complete_tx::bytes [%0], [%1], %2, [%3];"
        :: "r"(dst), "l"(src), "r"(bytes), "r"(mbar) : "memory");
}
__device__ __forceinline__ void mbar_wait0(uint32_t mb) {
    asm volatile(
        "{ .reg .pred P;\n"
        "W_%=: mbarrier.try_wait.parity.acquire.cta.shared::cta.b64 P, [%0], 0, 0x989680;\n"
        "@P bra.uni D_%=;\n bra.uni W_%=;\n D_%=: }" :: "r"(mb) : "memory");
}

// =================================================================================
// Kernel 0: detect edge_index dtype (int32 vs int64).
// =================================================================================
__global__ void detect_kernel(const void* ei_raw, int E)
{
    const long long* e64 = (const long long*)ei_raw;
    int n = E < 64 ? E : 64;
    int ok = 1;
    for (int i = 0; i < n; i++) {
        long long v = e64[i];
        if (v < 0 || v >= N_NODES) { ok = 0; break; }
    }
    g_is64 = ok;
}

__device__ __forceinline__ void load_edge(const void* ei_raw, int E, int e,
                                          int& src, int& dst)
{
    if (g_is64) {
        const long long* p = (const long long*)ei_raw;
        src = (int)p[e];
        dst = (int)p[(size_t)E + e];
    } else {
        const int* p = (const int*)ei_raw;
        src = p[e];
        dst = p[E + e];
    }
}

// =================================================================================
// Kernel A: x packed planes + attention pre-dots + zeroing.
// =================================================================================
__global__ __launch_bounds__(256) void node_pre_kernel(
    const float* __restrict__ x, const float* __restrict__ W_att)
{
    __shared__ __align__(16) float xs[64][132];
    __shared__ float Was[128], Wad[128];

    const int tid = threadIdx.x;
    const int n0  = blockIdx.x * 64;

    if (tid < 128) { Was[tid] = W_att[tid]; Wad[tid] = W_att[128 + tid]; }
    if (tid < 64) g_cnt[n0 + tid] = 0;
    if (blockIdx.x == 0 && tid < 128) {
        g_sum[tid] = 0.f; g_ssq[tid] = 0.f; g_cnt[NP + tid] = 0;
    }

    for (int i = tid; i < 64 * 32; i += 256) {
        int node = i >> 5, cq = i & 31;
        float4 v = make_float4(0.f, 0.f, 0.f, 0.f);
        int gn = n0 + node;
        if (gn < N_NODES) v = *(const float4*)&x[(size_t)gn * D + cq * 4];
        *(float4*)&xs[node][cq * 4] = v;
        __nv_bfloat162 h01, h23, l01, l23;
        f2bf(v.x, h01.x, l01.x); f2bf(v.y, h01.y, l01.y);
        f2bf(v.z, h23.x, l23.x); f2bf(v.w, h23.y, l23.y);
        size_t ro = (size_t)gn * ROWB;
        *(__nv_bfloat162*)&g_xP[ro + cq * 4]           = h01;
        *(__nv_bfloat162*)&g_xP[ro + cq * 4 + 2]       = h23;
        *(__nv_bfloat162*)&g_xP[ro + 128 + cq * 4]     = l01;
        *(__nv_bfloat162*)&g_xP[ro + 128 + cq * 4 + 2] = l23;
    }
    __syncthreads();

    if (tid < 128) {
        int node = tid >> 1, sel = tid & 1;
        const float* wv = sel ? Wad : Was;
        float a0 = 0.f, a1 = 0.f, a2 = 0.f, a3 = 0.f;
#pragma unroll 8
        for (int k = 0; k < 128; k += 4) {
            a0 += xs[node][k]     * wv[k];
            a1 += xs[node][k + 1] * wv[k + 1];
            a2 += xs[node][k + 2] * wv[k + 2];
            a3 += xs[node][k + 3] * wv[k + 3];
        }
        float r = (a0 + a1) + (a2 + a3);
        if (sel) g_ad[n0 + node] = r; else g_as[n0 + node] = r;
    }
}

// =================================================================================
// Convert weights -> packed plane rows.
// Rows 0..383: W_ih; 384..767: W_hh; 768..895: W_msg^T.
// =================================================================================
#define CVT_W_Q (896 * 32)
__global__ __launch_bounds__(256) void convert_w_kernel(
    const float* __restrict__ W_ih, const float* __restrict__ W_hh,
    const float* __restrict__ W_msg)
{
    int idx = blockIdx.x * 256 + threadIdx.x;
    if (idx >= CVT_W_Q) return;
    int row = idx >> 5, cq = idx & 31;

    float4 v;
    if (row < 384) {
        v = *(const float4*)&W_ih[(size_t)row * D + cq * 4];
    } else if (row < 768) {
        v = *(const float4*)&W_hh[(size_t)(row - 384) * D + cq * 4];
    } else {
        int j = row - 768;
        int k = cq * 4;
        v.x = W_msg[(size_t)(k + 0) * D + j];
        v.y = W_msg[(size_t)(k + 1) * D + j];
        v.z = W_msg[(size_t)(k + 2) * D + j];
        v.w = W_msg[(size_t)(k + 3) * D + j];
    }
    __nv_bfloat162 h01, h23, l01, l23;
    f2bf(v.x, h01.x, l01.x); f2bf(v.y, h01.y, l01.y);
    f2bf(v.z, h23.x, l23.x); f2bf(v.w, h23.y, l23.y);
    size_t ro = (size_t)row * ROWB;
    *(__nv_bfloat162*)&g_wP[ro + cq * 4]           = h01;
    *(__nv_bfloat162*)&g_wP[ro + cq * 4 + 2]       = h23;
    *(__nv_bfloat162*)&g_wP[ro + 128 + cq * 4]     = l01;
    *(__nv_bfloat162*)&g_wP[ro + 128 + cq * 4 + 2] = l23;
}

// =================================================================================
// CSR build: histogram -> scan (3 kernels) -> scatter.
// =================================================================================
__global__ __launch_bounds__(256) void hist_kernel(const void* __restrict__ ei, int E)
{
    int e = blockIdx.x * 256 + threadIdx.x;
    if (e >= E) return;
    int src, dst;
    load_edge(ei, E, e, src, dst);
    if ((unsigned)dst >= N_NODES) return;
    atomicAdd(&g_cnt[dst], 1);
}

__global__ __launch_bounds__(256) void scan_a_kernel()
{
    __shared__ int sh[256];
    const int tid = threadIdx.x;
    int t = blockIdx.x * 256 + tid;
    int v = g_cnt[t];
    sh[tid] = v; __syncthreads();
#pragma unroll
    for (int o = 1; o < 256; o <<= 1) {
        int u = (tid >= o) ? sh[tid - o] : 0;
        __syncthreads();
        sh[tid] += u;
        __syncthreads();
    }
    g_off[t] = sh[tid] - v;
    if (tid == 255) g_bsum[blockIdx.x] = sh[255];
}

__global__ __launch_bounds__(256) void scan_b_kernel()
{
    __shared__ int sh[256];
    const int tid = threadIdx.x;
    int v = (tid < NSCAN / 256) ? g_bsum[tid] : 0;
    sh[tid] = v; __syncthreads();
#pragma unroll
    for (int o = 1; o < 256; o <<= 1) {
        int u = (tid >= o) ? sh[tid - o] : 0;
        __syncthreads();
        sh[tid] += u;
        __syncthreads();
    }
    g_boff[tid] = sh[tid] - v;
}

__global__ __launch_bounds__(256) void scan_c_kernel()
{
    int t = blockIdx.x * 256 + threadIdx.x;
    int s = g_off[t] + g_boff[blockIdx.x];
    g_start[t] = s;
    g_cur[t]   = s;
}

__global__ __launch_bounds__(256) void scatter_kernel(const void* __restrict__ ei, int E)
{
    int e = blockIdx.x * 256 + threadIdx.x;
    if (e >= E) return;
    int src, dst;
    load_edge(ei, E, e, src, dst);
    if ((unsigned)src >= N_NODES || (unsigned)dst >= N_NODES) return;
    int p = atomicAdd(&g_cur[dst], 1);
    if (p < E) g_esrc[p] = src;
}

// =================================================================================
// Gather: one warp per dst node; writes agg as packed planes.
// =================================================================================
__global__ __launch_bounds__(256) void gather_kernel(const float* __restrict__ b_att)
{
    const int wid  = threadIdx.x >> 5;
    const int lane = threadIdx.x & 31;
    const int n = blockIdx.x * 8 + wid;
    if (n >= NP) return;

    const int s0 = g_start[n];
    const int s1 = g_start[n + 1];
    const float adb = ((n < N_NODES) ? g_ad[n] : 0.f) + b_att[0];

    float4 acc = make_float4(0.f, 0.f, 0.f, 0.f);
    int i = s0;
    for (; i + 1 < s1; i += 2) {
        int src0 = g_esrc[i], src1 = g_esrc[i + 1];
        float at0 = sigm(g_as[src0] + adb);
        float at1 = sigm(g_as[src1] + adb);
        float4 v0 = *(const float4*)&g_m[(size_t)src0 * D + lane * 4];
        float4 v1 = *(const float4*)&g_m[(size_t)src1 * D + lane * 4];
        acc.x += v0.x * at0 + v1.x * at1;
        acc.y += v0.y * at0 + v1.y * at1;
        acc.z += v0.z * at0 + v1.z * at1;
        acc.w += v0.w * at0 + v1.w * at1;
    }
    if (i < s1) {
        int src0 = g_esrc[i];
        float at0 = sigm(g_as[src0] + adb);
        float4 v0 = *(const float4*)&g_m[(size_t)src0 * D + lane * 4];
        acc.x += v0.x * at0; acc.y += v0.y * at0;
        acc.z += v0.z * at0; acc.w += v0.w * at0;
    }
    __nv_bfloat162 h01, h23, l01, l23;
    f2bf(acc.x, h01.x, l01.x); f2bf(acc.y, h01.y, l01.y);
    f2bf(acc.z, h23.x, l23.x); f2bf(acc.w, h23.y, l23.y);
    size_t ro = (size_t)n * ROWB;
    *(__nv_bfloat162*)&g_agP[ro + lane * 4]           = h01;
    *(__nv_bfloat162*)&g_agP[ro + lane * 4 + 2]       = h23;
    *(__nv_bfloat162*)&g_agP[ro + 128 + lane * 4]     = l01;
    *(__nv_bfloat162*)&g_agP[ro + 128 + lane * 4 + 2] = l23;
}

// =================================================================================
// Split-bf16 GEMM with cp.async.bulk tile loads (one instr per 67.6KB tile).
// Packed global rows have the exact smem layout (stride 264 bf16, conflict-free).
// =================================================================================
#define AS_STR 264
#define TILE_BYTES (128 * ROWB * 2)        // 67584
#define SMEM_GEMM (3 * TILE_BYTES + 32)

__device__ __forceinline__ void mma16816(float* c, const uint32_t* a, const uint32_t* b) {
    asm volatile(
        "mma.sync.aligned.m16n8k16.row.col.f32.bf16.bf16.f32 "
        "{%0,%1,%2,%3}, {%4,%5,%6,%7}, {%8,%9}, {%0,%1,%2,%3};"
        : "+f"(c[0]), "+f"(c[1]), "+f"(c[2]), "+f"(c[3])
        : "r"(a[0]), "r"(a[1]), "r"(a[2]), "r"(a[3]), "r"(b[0]), "r"(b[1]));
}
__device__ __forceinline__ void ldmx4(uint32_t* d, uint32_t addr) {
    asm volatile("ldmatrix.sync.aligned.m8n8.x4.shared.b16 {%0,%1,%2,%3}, [%4];"
                 : "=r"(d[0]), "=r"(d[1]), "=r"(d[2]), "=r"(d[3]) : "r"(addr));
}

// compute one 128x128 tile from sA and sB. __noinline__: register barrier.
__device__ __noinline__ void gemm_tile(
    const __nv_bfloat16* sA, const __nv_bfloat16* sB,
    const float* __restrict__ bias, float* __restrict__ out,
    int ostride, int ocol0, int n0)
{
    const int tid  = threadIdx.x;
    const int wid  = tid >> 5;
    const int lane = tid & 31;
    const int wm = (wid & 3) * 32;
    const int wn = (wid >> 2) * 64;
    const int g  = lane >> 3;
    const int r  = lane & 7;
    const int qr = lane >> 2;
    const int qc = (lane & 3) * 2;

    uint32_t aBase[2], bBase[4];
#pragma unroll
    for (int mt = 0; mt < 2; mt++) {
        int row = wm + mt * 16 + ((g & 1) ? 8 : 0) + r;
        int col = (g >= 2) ? 8 : 0;
        aBase[mt] = smem_u32(&sA[row * AS_STR + col]);
    }
#pragma unroll
    for (int ntp = 0; ntp < 4; ntp++) {
        int row = wn + (ntp * 2 + (g >> 1)) * 8 + r;
        int col = (g & 1) ? 8 : 0;
        bBase[ntp] = smem_u32(&sB[row * AS_STR + col]);
    }

    float c[2][8][4];
#pragma unroll
    for (int mt = 0; mt < 2; mt++)
#pragma unroll
        for (int nt = 0; nt < 8; nt++)
#pragma unroll
            for (int j = 0; j < 4; j++) c[mt][nt][j] = 0.f;

#pragma unroll
    for (int pass = 0; pass < 3; pass++) {
        const int kA = (pass == 1) ? 128 : 0;
        const int kB = (pass == 2) ? 128 : 0;
#pragma unroll
        for (int s = 0; s < 8; s++) {
            const uint32_t offA = (uint32_t)((kA + s * 16) * 2);
            const uint32_t offB = (uint32_t)((kB + s * 16) * 2);
            uint32_t a[2][4], b[4][4];
            ldmx4(a[0], aBase[0] + offA);
            ldmx4(a[1], aBase[1] + offA);
#pragma unroll
            for (int ntp = 0; ntp < 4; ntp++) ldmx4(b[ntp], bBase[ntp] + offB);
#pragma unroll
            for (int mt = 0; mt < 2; mt++)
#pragma unroll
                for (int ntp = 0; ntp < 4; ntp++) {
                    mma16816(c[mt][ntp * 2],     a[mt], &b[ntp][0]);
                    mma16816(c[mt][ntp * 2 + 1], a[mt], &b[ntp][2]);
                }
        }
    }

#pragma unroll
    for (int mt = 0; mt < 2; mt++) {
#pragma unroll
        for (int nt = 0; nt < 8; nt++) {
            int col = wn + nt * 8 + qc;
            float b0 = bias[col], b1 = bias[col + 1];
            int r0 = n0 + wm + mt * 16 + qr;
            size_t g0 = (size_t)r0 * ostride + ocol0 + col;
            size_t g1 = (size_t)(r0 + 8) * ostride + ocol0 + col;
            *(float2*)&out[g0] = make_float2(c[mt][nt][0] + b0, c[mt][nt][1] + b1);
            *(float2*)&out[g1] = make_float2(c[mt][nt][2] + b0, c[mt][nt][3] + b1);
        }
    }
}

// pair driver: bulk-load B + A(t0) [mbar0], A(t1) [mbar1], compute both.
__device__ __forceinline__ void gemm_pair(
    const __nv_bfloat16* __restrict__ AP, int brow0,
    const float* __restrict__ bias, float* __restrict__ out,
    int ostride, int ocol0, int t0, char* smem)
{
    __nv_bfloat16* sB  = (__nv_bfloat16*)smem;
    __nv_bfloat16* sA0 = (__nv_bfloat16*)(smem + TILE_BYTES);
    __nv_bfloat16* sA1 = (__nv_bfloat16*)(smem + 2 * TILE_BYTES);
    const uint32_t sb = smem_u32(smem);
    const uint32_t mb0 = sb + 3 * TILE_BYTES;
    const uint32_t mb1 = mb0 + 8;
    const int tid = threadIdx.x;
    const int t1 = t0 + 1;
    const bool has2 = (t1 < NT);

    if (tid == 0) { MBAR_INIT(mb0, 1); MBAR_INIT(mb1, 1); }
    __syncthreads();

    if (tid == 0) {
        MBAR_EXPECT_TX(mb0, 2 * TILE_BYTES);
        bulk_ld(sb, &g_wP[(size_t)brow0 * ROWB], TILE_BYTES, mb0);
        bulk_ld(sb + TILE_BYTES, &AP[(size_t)t0 * 128 * ROWB], TILE_BYTES, mb0);
        if (has2) {
            MBAR_EXPECT_TX(mb1, TILE_BYTES);
            bulk_ld(sb + 2 * TILE_BYTES, &AP[(size_t)t1 * 128 * ROWB], TILE_BYTES, mb1);
        }
    }

    mbar_wait0(mb0);
    gemm_tile(sA0, sB, bias, out, ostride, ocol0, t0 * 128);

    if (has2) {
        mbar_wait0(mb1);
        gemm_tile(sA1, sB, bias, out, ostride, ocol0, t1 * 128);
    }
}

__global__ __launch_bounds__(256) void gemm_main_kernel(
    const float* __restrict__ b_ih, const float* __restrict__ b_hh)
{
    extern __shared__ __align__(128) char smem[];
    const int bx = blockIdx.x;
    const bool ih = (bx < 3);
    gemm_pair(ih ? g_agP : g_xP,
              bx * 128,
              ih ? (b_ih + bx * 128) : (b_hh + (bx - 3) * 128),
              g_g, 768, bx * 128, blockIdx.y * 2, smem);
}

__global__ __launch_bounds__(256) void gemm_msg_kernel(const float* __restrict__ b_msg)
{
    extern __shared__ __align__(128) char smem[];
    gemm_pair(g_xP, 768, b_msg, g_m, 128, 0, blockIdx.x * 2, smem);
}

// =================================================================================
// Kernel D: GRU elementwise + BN column-stat accumulation.
// =================================================================================
__global__ __launch_bounds__(256) void gru_kernel(const float* __restrict__ x)
{
    __shared__ float rs_[8][128];
    __shared__ float rq_[8][128];

    const int tid = threadIdx.x;
    const int c4 = tid & 31;
    const int rs = tid >> 5;
    float4 s = make_float4(0.f, 0.f, 0.f, 0.f);
    float4 q = make_float4(0.f, 0.f, 0.f, 0.f);

    for (int it = 0; it < 16; it++) {
        int n = blockIdx.x * 128 + it * 8 + rs;
        if (n >= N_NODES) break;
        size_t gb = (size_t)n * 768 + c4 * 4;
        float4 ir = *(const float4*)&g_g[gb];
        float4 iz = *(const float4*)&g_g[gb + 128];
        float4 in_ = *(const float4*)&g_g[gb + 256];
        float4 hr = *(const float4*)&g_g[gb + 384];
        float4 hz = *(const float4*)&g_g[gb + 512];
        float4 hn = *(const float4*)&g_g[gb + 640];
        float4 xv = *(const float4*)&x[(size_t)n * D + c4 * 4];

        float4 h;
        {
            float r = sigm(ir.x + hr.x), z = sigm(iz.x + hz.x);
            float nn = tanhf(in_.x + r * hn.x); h.x = (1.f - z) * nn + z * xv.x;
        }
        {
            float r = sigm(ir.y + hr.y), z = sigm(iz.y + hz.y);
            float nn = tanhf(in_.y + r * hn.y); h.y = (1.f - z) * nn + z * xv.y;
        }
        {
            float r = sigm(ir.z + hr.z), z = sigm(iz.z + hz.z);
            float nn = tanhf(in_.z + r * hn.z); h.z = (1.f - z) * nn + z * xv.z;
        }
        {
            float r = sigm(ir.w + hr.w), z = sigm(iz.w + hz.w);
            float nn = tanhf(in_.w + r * hn.w); h.w = (1.f - z) * nn + z * xv.w;
        }
        *(float4*)&g_h[(size_t)n * D + c4 * 4] = h;
        s.x += h.x; s.y += h.y; s.z += h.z; s.w += h.w;
        q.x += h.x * h.x; q.y += h.y * h.y; q.z += h.z * h.z; q.w += h.w * h.w;
    }

    *(float4*)&rs_[rs][c4 * 4] = s;
    *(float4*)&rq_[rs][c4 * 4] = q;
    __syncthreads();
    if (tid < 128) {
        float a = 0.f, b = 0.f;
#pragma unroll
        for (int r = 0; r < 8; r++) { a += rs_[r][tid]; b += rq_[r][tid]; }
        atomicAdd(&g_sum[tid], a);
        atomicAdd(&g_ssq[tid], b);
    }
}

// =================================================================================
// Kernel E: BatchNorm normalize.
// =================================================================================
__global__ __launch_bounds__(256) void bn_kernel(
    const float* __restrict__ gamma, const float* __restrict__ beta,
    float* __restrict__ out)
{
    int idx = blockIdx.x * 256 + threadIdx.x;
    if (idx >= N_NODES * 32) return;
    int c4 = idx & 31;
    const float inv_n = 1.f / (float)N_NODES;

    float4 h  = *(const float4*)&g_h[(size_t)idx * 4];
    float4 sm = *(const float4*)&g_sum[c4 * 4];
    float4 sq = *(const float4*)&g_ssq[c4 * 4];
    float4 ga = *(const float4*)&gamma[c4 * 4];
    float4 be = *(const float4*)&beta[c4 * 4];

    float4 o;
    {
        float mean = sm.x * inv_n; float var = sq.x * inv_n - mean * mean;
        o.x = ga.x * (h.x - mean) * rsqrtf(var + BN_EPS) + be.x;
    }
    {
        float mean = sm.y * inv_n; float var = sq.y * inv_n - mean * mean;
        o.y = ga.y * (h.y - mean) * rsqrtf(var + BN_EPS) + be.y;
    }
    {
        float mean = sm.z * inv_n; float var = sq.z * inv_n - mean * mean;
        o.z = ga.z * (h.z - mean) * rsqrtf(var + BN_EPS) + be.z;
    }
    {
        float mean = sm.w * inv_n; float var = sq.w * inv_n - mean * mean;
        o.w = ga.w * (h.w - mean) * rsqrtf(var + BN_EPS) + be.w;
    }
    *(float4*)&out[(size_t)idx * 4] = o;
}

// =================================================================================
extern "C" void kernel_launch(void* const* d_in, const int* in_sizes, int n_in,
                              void* d_out, int out_size)
{
    const float* x     = (const float*)d_in[0];
    const void*  ei    = d_in[1];
    const float* W_msg = (const float*)d_in[2];
    const float* b_msg = (const float*)d_in[3];
    const float* W_att = (const float*)d_in[4];
    const float* b_att = (const float*)d_in[5];
    const float* W_ih  = (const float*)d_in[6];
    const float* b_ih  = (const float*)d_in[7];
    const float* W_hh  = (const float*)d_in[8];
    const float* b_hh  = (const float*)d_in[9];
    const float* gamma = (const float*)d_in[10];
    const float* beta  = (const float*)d_in[11];
    float* out = (float*)d_out;

    const int E = in_sizes[1] / 2;
    const int PAIRS = (NT + 1) / 2;   // 196

    static int smem_set = 0;
    if (!smem_set) {
        cudaFuncSetAttribute(gemm_main_kernel,
                             cudaFuncAttributeMaxDynamicSharedMemorySize, SMEM_GEMM);
        cudaFuncSetAttribute(gemm_msg_kernel,
                             cudaFuncAttributeMaxDynamicSharedMemorySize, SMEM_GEMM);
        smem_set = 1;
    }

    detect_kernel<<<1, 1>>>(ei, E);
    node_pre_kernel<<<NP / 64, 256>>>(x, W_att);
    convert_w_kernel<<<(CVT_W_Q + 255) / 256, 256>>>(W_ih, W_hh, W_msg);
    gemm_msg_kernel<<<PAIRS, 256, SMEM_GEMM>>>(b_msg);
    hist_kernel<<<(E + 255) / 256, 256>>>(ei, E);
    scan_a_kernel<<<NSCAN / 256, 256>>>();
    scan_b_kernel<<<1, 256>>>();
    scan_c_kernel<<<NSCAN / 256, 256>>>();
    scatter_kernel<<<(E + 255) / 256, 256>>>(ei, E);
    gather_kernel<<<(NP + 7) / 8, 256>>>(b_att);
    gemm_main_kernel<<<dim3(6, PAIRS), 256, SMEM_GEMM>>>(b_ih, b_hh);
    gru_kernel<<<NP / 128, 256>>>(x);
    bn_kernel<<<(N_NODES * 32 + 255) / 256, 256>>>(gamma, beta, out);
}

// round 13
// speedup vs baseline: 1.5348x; 1.0239x over previous
#include <cuda_runtime.h>
#include <cuda_bf16.h>
#include <cstdint>
#include <cstddef>

// Problem constants
#define N_NODES 50000
#define NP      50048          // padded: 782*64 = 391*128
#define NSCAN   50176          // NP + 128, = 196*256 for scan
#define NT      391            // node tiles of 128
#define D       128
#define E_MAX   800000
#define BN_EPS  1e-5f
#define ROWB    264            // bf16 per packed row: [hi 128 | lo 128 | pad 8]

// ---------------- scratch (static device globals; no runtime alloc) -------------
__device__ float g_m  [(size_t)NP * D];
__device__ float g_as [NP];
__device__ float g_ad [NP];
__device__ float g_g  [(size_t)NP * 768];
__device__ float g_h  [(size_t)NP * D];
__device__ float g_sum[D];
__device__ float g_ssq[D];
__device__ int   g_is64;

// CSR build for edge gather
__device__ int g_cnt [NSCAN];
__device__ int g_off [NSCAN];
__device__ int g_bsum[256];
__device__ int g_boff[256];
__device__ int g_start[NSCAN];
__device__ int g_cur [NSCAN];
__device__ int g_esrc[E_MAX];

// packed bf16 hi|lo planes (row stride ROWB, smem-identical layout for bulk copy)
__device__ __align__(128) __nv_bfloat16 g_xP [(size_t)NP * ROWB];
__device__ __align__(128) __nv_bfloat16 g_agP[(size_t)NP * ROWB];
__device__ __align__(128) __nv_bfloat16 g_wP [896 * ROWB];  // [W_ih(384);W_hh(384);W_msg^T(128)]

__device__ __forceinline__ float sigm(float v) { return 1.f / (1.f + __expf(-v)); }

__device__ __forceinline__ uint32_t smem_u32(const void* p) {
    uint32_t a;
    asm("{ .reg .u64 t; cvta.to.shared.u64 t, %1; cvt.u32.u64 %0, t; }" : "=r"(a) : "l"(p));
    return a;
}
__device__ __forceinline__ void f2bf(float v, __nv_bfloat16& h, __nv_bfloat16& l) {
    h = __float2bfloat16(v);
    l = __float2bfloat16(v - __bfloat162float(h));
}

#define MBAR_INIT(mb, c) asm volatile("mbarrier.init.shared.b64 [%0], %1;" :: "r"(mb), "r"(c) : "memory")
#define MBAR_EXPECT_TX(mb, n) asm volatile("mbarrier.arrive.expect_tx.shared.b64 _, [%0], %1;" :: "r"(mb), "r"(n) : "memory")
__device__ __forceinline__ void bulk_ld(uint32_t dst, const void* src, uint32_t bytes, uint32_t mbar) {
    asm volatile(
        "cp.async.bulk.shared::cta.global.mbarrier::complete_tx::bytes [%0], [%1], %2, [%3];"
        :: "r"(dst), "l"(src), "r"(bytes), "r"(mbar) : "memory");
}
__device__ __forceinline__ void mbar_wait0(uint32_t mb) {
    asm volatile(
        "{ .reg .pred P;\n"
        "W_%=: mbarrier.try_wait.parity.acquire.cta.shared::cta.b64 P, [%0], 0, 0x989680;\n"
        "@P bra.uni D_%=;\n bra.uni W_%=;\n D_%=: }" :: "r"(mb) : "memory");
}

// =================================================================================
// Kernel 0: detect edge_index dtype (int32 vs int64).
// =================================================================================
__global__ void detect_kernel(const void* ei_raw, int E)
{
    const long long* e64 = (const long long*)ei_raw;
    int n = E < 64 ? E : 64;
    int ok = 1;
    for (int i = 0; i < n; i++) {
        long long v = e64[i];
        if (v < 0 || v >= N_NODES) { ok = 0; break; }
    }
    g_is64 = ok;
}

__device__ __forceinline__ void load_edge(const void* ei_raw, int E, int e,
                                          int& src, int& dst)
{
    if (g_is64) {
        const long long* p = (const long long*)ei_raw;
        src = (int)p[e];
        dst = (int)p[(size_t)E + e];
    } else {
        const int* p = (const int*)ei_raw;
        src = p[e];
        dst = p[E + e];
    }
}

// =================================================================================
// Kernel A: x packed planes + attention pre-dots + zeroing.
// =================================================================================
__global__ __launch_bounds__(256) void node_pre_kernel(
    const float* __restrict__ x, const float* __restrict__ W_att)
{
    __shared__ __align__(16) float xs[64][132];
    __shared__ float Was[128], Wad[128];

    const int tid = threadIdx.x;
    const int n0  = blockIdx.x * 64;

    if (tid < 128) { Was[tid] = W_att[tid]; Wad[tid] = W_att[128 + tid]; }
    if (tid < 64) g_cnt[n0 + tid] = 0;
    if (blockIdx.x == 0 && tid < 128) {
        g_sum[tid] = 0.f; g_ssq[tid] = 0.f; g_cnt[NP + tid] = 0;
    }

    for (int i = tid; i < 64 * 32; i += 256) {
        int node = i >> 5, cq = i & 31;
        float4 v = make_float4(0.f, 0.f, 0.f, 0.f);
        int gn = n0 + node;
        if (gn < N_NODES) v = *(const float4*)&x[(size_t)gn * D + cq * 4];
        *(float4*)&xs[node][cq * 4] = v;
        __nv_bfloat162 h01, h23, l01, l23;
        f2bf(v.x, h01.x, l01.x); f2bf(v.y, h01.y, l01.y);
        f2bf(v.z, h23.x, l23.x); f2bf(v.w, h23.y, l23.y);
        size_t ro = (size_t)gn * ROWB;
        *(__nv_bfloat162*)&g_xP[ro + cq * 4]           = h01;
        *(__nv_bfloat162*)&g_xP[ro + cq * 4 + 2]       = h23;
        *(__nv_bfloat162*)&g_xP[ro + 128 + cq * 4]     = l01;
        *(__nv_bfloat162*)&g_xP[ro + 128 + cq * 4 + 2] = l23;
    }
    __syncthreads();

    if (tid < 128) {
        int node = tid >> 1, sel = tid & 1;
        const float* wv = sel ? Wad : Was;
        float a0 = 0.f, a1 = 0.f, a2 = 0.f, a3 = 0.f;
#pragma unroll 8
        for (int k = 0; k < 128; k += 4) {
            a0 += xs[node][k]     * wv[k];
            a1 += xs[node][k + 1] * wv[k + 1];
            a2 += xs[node][k + 2] * wv[k + 2];
            a3 += xs[node][k + 3] * wv[k + 3];
        }
        float r = (a0 + a1) + (a2 + a3);
        if (sel) g_ad[n0 + node] = r; else g_as[n0 + node] = r;
    }
}

// =================================================================================
// Convert weights -> packed plane rows.
// =================================================================================
#define CVT_W_Q (896 * 32)
__global__ __launch_bounds__(256) void convert_w_kernel(
    const float* __restrict__ W_ih, const float* __restrict__ W_hh,
    const float* __restrict__ W_msg)
{
    int idx = blockIdx.x * 256 + threadIdx.x;
    if (idx >= CVT_W_Q) return;
    int row = idx >> 5, cq = idx & 31;

    float4 v;
    if (row < 384) {
        v = *(const float4*)&W_ih[(size_t)row * D + cq * 4];
    } else if (row < 768) {
        v = *(const float4*)&W_hh[(size_t)(row - 384) * D + cq * 4];
    } else {
        int j = row - 768;
        int k = cq * 4;
        v.x = W_msg[(size_t)(k + 0) * D + j];
        v.y = W_msg[(size_t)(k + 1) * D + j];
        v.z = W_msg[(size_t)(k + 2) * D + j];
        v.w = W_msg[(size_t)(k + 3) * D + j];
    }
    __nv_bfloat162 h01, h23, l01, l23;
    f2bf(v.x, h01.x, l01.x); f2bf(v.y, h01.y, l01.y);
    f2bf(v.z, h23.x, l23.x); f2bf(v.w, h23.y, l23.y);
    size_t ro = (size_t)row * ROWB;
    *(__nv_bfloat162*)&g_wP[ro + cq * 4]           = h01;
    *(__nv_bfloat162*)&g_wP[ro + cq * 4 + 2]       = h23;
    *(__nv_bfloat162*)&g_wP[ro + 128 + cq * 4]     = l01;
    *(__nv_bfloat162*)&g_wP[ro + 128 + cq * 4 + 2] = l23;
}

// =================================================================================
// CSR build: histogram -> scan (3 kernels) -> scatter.
// =================================================================================
__global__ __launch_bounds__(256) void hist_kernel(const void* __restrict__ ei, int E)
{
    int e = blockIdx.x * 256 + threadIdx.x;
    if (e >= E) return;
    int src, dst;
    load_edge(ei, E, e, src, dst);
    if ((unsigned)dst >= N_NODES) return;
    atomicAdd(&g_cnt[dst], 1);
}

__global__ __launch_bounds__(256) void scan_a_kernel()
{
    __shared__ int sh[256];
    const int tid = threadIdx.x;
    int t = blockIdx.x * 256 + tid;
    int v = g_cnt[t];
    sh[tid] = v; __syncthreads();
#pragma unroll
    for (int o = 1; o < 256; o <<= 1) {
        int u = (tid >= o) ? sh[tid - o] : 0;
        __syncthreads();
        sh[tid] += u;
        __syncthreads();
    }
    g_off[t] = sh[tid] - v;
    if (tid == 255) g_bsum[blockIdx.x] = sh[255];
}

__global__ __launch_bounds__(256) void scan_b_kernel()
{
    __shared__ int sh[256];
    const int tid = threadIdx.x;
    int v = (tid < NSCAN / 256) ? g_bsum[tid] : 0;
    sh[tid] = v; __syncthreads();
#pragma unroll
    for (int o = 1; o < 256; o <<= 1) {
        int u = (tid >= o) ? sh[tid - o] : 0;
        __syncthreads();
        sh[tid] += u;
        __syncthreads();
    }
    g_boff[tid] = sh[tid] - v;
}

__global__ __launch_bounds__(256) void scan_c_kernel()
{
    int t = blockIdx.x * 256 + threadIdx.x;
    int s = g_off[t] + g_boff[blockIdx.x];
    g_start[t] = s;
    g_cur[t]   = s;
}

__global__ __launch_bounds__(256) void scatter_kernel(const void* __restrict__ ei, int E)
{
    int e = blockIdx.x * 256 + threadIdx.x;
    if (e >= E) return;
    int src, dst;
    load_edge(ei, E, e, src, dst);
    if ((unsigned)src >= N_NODES || (unsigned)dst >= N_NODES) return;
    int p = atomicAdd(&g_cur[dst], 1);
    if (p < E) g_esrc[p] = src;
}

// =================================================================================
// Gather: one warp per dst node; writes agg as packed planes.
// =================================================================================
__global__ __launch_bounds__(256) void gather_kernel(const float* __restrict__ b_att)
{
    const int wid  = threadIdx.x >> 5;
    const int lane = threadIdx.x & 31;
    const int n = blockIdx.x * 8 + wid;
    if (n >= NP) return;

    const int s0 = g_start[n];
    const int s1 = g_start[n + 1];
    const float adb = ((n < N_NODES) ? g_ad[n] : 0.f) + b_att[0];

    float4 acc = make_float4(0.f, 0.f, 0.f, 0.f);
    int i = s0;
    for (; i + 1 < s1; i += 2) {
        int src0 = g_esrc[i], src1 = g_esrc[i + 1];
        float at0 = sigm(g_as[src0] + adb);
        float at1 = sigm(g_as[src1] + adb);
        float4 v0 = *(const float4*)&g_m[(size_t)src0 * D + lane * 4];
        float4 v1 = *(const float4*)&g_m[(size_t)src1 * D + lane * 4];
        acc.x += v0.x * at0 + v1.x * at1;
        acc.y += v0.y * at0 + v1.y * at1;
        acc.z += v0.z * at0 + v1.z * at1;
        acc.w += v0.w * at0 + v1.w * at1;
    }
    if (i < s1) {
        int src0 = g_esrc[i];
        float at0 = sigm(g_as[src0] + adb);
        float4 v0 = *(const float4*)&g_m[(size_t)src0 * D + lane * 4];
        acc.x += v0.x * at0; acc.y += v0.y * at0;
        acc.z += v0.z * at0; acc.w += v0.w * at0;
    }
    __nv_bfloat162 h01, h23, l01, l23;
    f2bf(acc.x, h01.x, l01.x); f2bf(acc.y, h01.y, l01.y);
    f2bf(acc.z, h23.x, l23.x); f2bf(acc.w, h23.y, l23.y);
    size_t ro = (size_t)n * ROWB;
    *(__nv_bfloat162*)&g_agP[ro + lane * 4]           = h01;
    *(__nv_bfloat162*)&g_agP[ro + lane * 4 + 2]       = h23;
    *(__nv_bfloat162*)&g_agP[ro + 128 + lane * 4]     = l01;
    *(__nv_bfloat162*)&g_agP[ro + 128 + lane * 4 + 2] = l23;
}

// =================================================================================
// Split-bf16 GEMM, quad-tile blocks: one resident B, 4 node tiles, 2 A buffers,
// one single-use mbarrier per tile (no phase tracking). A(i+2) bulk-load is
// issued after tile i completes, hiding under tile i+1 compute.
// =================================================================================
#define AS_STR 264
#define TILE_BYTES (128 * ROWB * 2)        // 67584
#define SMEM_GEMM (3 * TILE_BYTES + 64)
#define TPB 4                               // tiles per block

__device__ __forceinline__ void mma16816(float* c, const uint32_t* a, const uint32_t* b) {
    asm volatile(
        "mma.sync.aligned.m16n8k16.row.col.f32.bf16.bf16.f32 "
        "{%0,%1,%2,%3}, {%4,%5,%6,%7}, {%8,%9}, {%0,%1,%2,%3};"
        : "+f"(c[0]), "+f"(c[1]), "+f"(c[2]), "+f"(c[3])
        : "r"(a[0]), "r"(a[1]), "r"(a[2]), "r"(a[3]), "r"(b[0]), "r"(b[1]));
}
__device__ __forceinline__ void ldmx4(uint32_t* d, uint32_t addr) {
    asm volatile("ldmatrix.sync.aligned.m8n8.x4.shared.b16 {%0,%1,%2,%3}, [%4];"
                 : "=r"(d[0]), "=r"(d[1]), "=r"(d[2]), "=r"(d[3]) : "r"(addr));
}

// compute one 128x128 tile from sA and sB. __noinline__: register barrier.
__device__ __noinline__ void gemm_tile(
    const __nv_bfloat16* sA, const __nv_bfloat16* sB,
    const float* __restrict__ bias, float* __restrict__ out,
    int ostride, int ocol0, int n0)
{
    const int tid  = threadIdx.x;
    const int wid  = tid >> 5;
    const int lane = tid & 31;
    const int wm = (wid & 3) * 32;
    const int wn = (wid >> 2) * 64;
    const int g  = lane >> 3;
    const int r  = lane & 7;
    const int qr = lane >> 2;
    const int qc = (lane & 3) * 2;

    uint32_t aBase[2], bBase[4];
#pragma unroll
    for (int mt = 0; mt < 2; mt++) {
        int row = wm + mt * 16 + ((g & 1) ? 8 : 0) + r;
        int col = (g >= 2) ? 8 : 0;
        aBase[mt] = smem_u32(&sA[row * AS_STR + col]);
    }
#pragma unroll
    for (int ntp = 0; ntp < 4; ntp++) {
        int row = wn + (ntp * 2 + (g >> 1)) * 8 + r;
        int col = (g & 1) ? 8 : 0;
        bBase[ntp] = smem_u32(&sB[row * AS_STR + col]);
    }

    float c[2][8][4];
#pragma unroll
    for (int mt = 0; mt < 2; mt++)
#pragma unroll
        for (int nt = 0; nt < 8; nt++)
#pragma unroll
            for (int j = 0; j < 4; j++) c[mt][nt][j] = 0.f;

#pragma unroll
    for (int pass = 0; pass < 3; pass++) {
        const int kA = (pass == 1) ? 128 : 0;
        const int kB = (pass == 2) ? 128 : 0;
#pragma unroll
        for (int s = 0; s < 8; s++) {
            const uint32_t offA = (uint32_t)((kA + s * 16) * 2);
            const uint32_t offB = (uint32_t)((kB + s * 16) * 2);
            uint32_t a[2][4], b[4][4];
            ldmx4(a[0], aBase[0] + offA);
            ldmx4(a[1], aBase[1] + offA);
#pragma unroll
            for (int ntp = 0; ntp < 4; ntp++) ldmx4(b[ntp], bBase[ntp] + offB);
#pragma unroll
            for (int mt = 0; mt < 2; mt++)
#pragma unroll
                for (int ntp = 0; ntp < 4; ntp++) {
                    mma16816(c[mt][ntp * 2],     a[mt], &b[ntp][0]);
                    mma16816(c[mt][ntp * 2 + 1], a[mt], &b[ntp][2]);
                }
        }
    }

#pragma unroll
    for (int mt = 0; mt < 2; mt++) {
#pragma unroll
        for (int nt = 0; nt < 8; nt++) {
            int col = wn + nt * 8 + qc;
            float b0 = bias[col], b1 = bias[col + 1];
            int r0 = n0 + wm + mt * 16 + qr;
            size_t g0 = (size_t)r0 * ostride + ocol0 + col;
            size_t g1 = (size_t)(r0 + 8) * ostride + ocol0 + col;
            *(float2*)&out[g0] = make_float2(c[mt][nt][0] + b0, c[mt][nt][1] + b1);
            *(float2*)&out[g1] = make_float2(c[mt][nt][2] + b0, c[mt][nt][3] + b1);
        }
    }
}

// quad driver: B resident; tiles t0..t0+3 (bounded by NT), 2 A buffers.
__device__ __forceinline__ void gemm_quad(
    const __nv_bfloat16* __restrict__ AP, int brow0,
    const float* __restrict__ bias, float* __restrict__ out,
    int ostride, int ocol0, int t0, char* smem)
{
    __nv_bfloat16* sB = (__nv_bfloat16*)smem;
    __nv_bfloat16* sA[2] = { (__nv_bfloat16*)(smem + TILE_BYTES),
                             (__nv_bfloat16*)(smem + 2 * TILE_BYTES) };
    const uint32_t sb = smem_u32(smem);
    const uint32_t mb = sb + 3 * TILE_BYTES;   // 4 mbarriers, 8B each
    const int tid = threadIdx.x;
    const int cnt = (NT - t0 < TPB) ? (NT - t0) : TPB;

    if (tid == 0) {
#pragma unroll
        for (int i = 0; i < TPB; i++) MBAR_INIT(mb + i * 8, 1);
    }
    __syncthreads();

    if (tid == 0) {
        MBAR_EXPECT_TX(mb, 2 * TILE_BYTES);
        bulk_ld(sb, &g_wP[(size_t)brow0 * ROWB], TILE_BYTES, mb);
        bulk_ld(sb + TILE_BYTES, &AP[(size_t)t0 * 128 * ROWB], TILE_BYTES, mb);
        if (cnt > 1) {
            MBAR_EXPECT_TX(mb + 8, TILE_BYTES);
            bulk_ld(sb + 2 * TILE_BYTES, &AP[(size_t)(t0 + 1) * 128 * ROWB],
                    TILE_BYTES, mb + 8);
        }
    }

    for (int i = 0; i < cnt; i++) {
        mbar_wait0(mb + i * 8);
        gemm_tile(sA[i & 1], sB, bias, out, ostride, ocol0, (t0 + i) * 128);
        if (i + 2 < cnt) {
            __syncthreads();               // all threads done reading sA[i&1]
            if (tid == 0) {
                MBAR_EXPECT_TX(mb + (i + 2) * 8, TILE_BYTES);
                bulk_ld(sb + (1 + (i & 1)) * TILE_BYTES,
                        &AP[(size_t)(t0 + i + 2) * 128 * ROWB],
                        TILE_BYTES, mb + (i + 2) * 8);
            }
        }
    }
}

__global__ __launch_bounds__(256) void gemm_main_kernel(
    const float* __restrict__ b_ih, const float* __restrict__ b_hh)
{
    extern __shared__ __align__(128) char smem[];
    const int bx = blockIdx.x;
    const bool ih = (bx < 3);
    gemm_quad(ih ? g_agP : g_xP,
              bx * 128,
              ih ? (b_ih + bx * 128) : (b_hh + (bx - 3) * 128),
              g_g, 768, bx * 128, blockIdx.y * TPB, smem);
}

__global__ __launch_bounds__(256) void gemm_msg_kernel(const float* __restrict__ b_msg)
{
    extern __shared__ __align__(128) char smem[];
    gemm_quad(g_xP, 768, b_msg, g_m, 128, 0, blockIdx.x * TPB, smem);
}

// =================================================================================
// Kernel D: GRU elementwise + BN column-stat accumulation.
// =================================================================================
__global__ __launch_bounds__(256) void gru_kernel(const float* __restrict__ x)
{
    __shared__ float rs_[8][128];
    __shared__ float rq_[8][128];

    const int tid = threadIdx.x;
    const int c4 = tid & 31;
    const int rs = tid >> 5;
    float4 s = make_float4(0.f, 0.f, 0.f, 0.f);
    float4 q = make_float4(0.f, 0.f, 0.f, 0.f);

    for (int it = 0; it < 16; it++) {
        int n = blockIdx.x * 128 + it * 8 + rs;
        if (n >= N_NODES) break;
        size_t gb = (size_t)n * 768 + c4 * 4;
        float4 ir = *(const float4*)&g_g[gb];
        float4 iz = *(const float4*)&g_g[gb + 128];
        float4 in_ = *(const float4*)&g_g[gb + 256];
        float4 hr = *(const float4*)&g_g[gb + 384];
        float4 hz = *(const float4*)&g_g[gb + 512];
        float4 hn = *(const float4*)&g_g[gb + 640];
        float4 xv = *(const float4*)&x[(size_t)n * D + c4 * 4];

        float4 h;
        {
            float r = sigm(ir.x + hr.x), z = sigm(iz.x + hz.x);
            float nn = tanhf(in_.x + r * hn.x); h.x = (1.f - z) * nn + z * xv.x;
        }
        {
            float r = sigm(ir.y + hr.y), z = sigm(iz.y + hz.y);
            float nn = tanhf(in_.y + r * hn.y); h.y = (1.f - z) * nn + z * xv.y;
        }
        {
            float r = sigm(ir.z + hr.z), z = sigm(iz.z + hz.z);
            float nn = tanhf(in_.z + r * hn.z); h.z = (1.f - z) * nn + z * xv.z;
        }
        {
            float r = sigm(ir.w + hr.w), z = sigm(iz.w + hz.w);
            float nn = tanhf(in_.w + r * hn.w); h.w = (1.f - z) * nn + z * xv.w;
        }
        *(float4*)&g_h[(size_t)n * D + c4 * 4] = h;
        s.x += h.x; s.y += h.y; s.z += h.z; s.w += h.w;
        q.x += h.x * h.x; q.y += h.y * h.y; q.z += h.z * h.z; q.w += h.w * h.w;
    }

    *(float4*)&rs_[rs][c4 * 4] = s;
    *(float4*)&rq_[rs][c4 * 4] = q;
    __syncthreads();
    if (tid < 128) {
        float a = 0.f, b = 0.f;
#pragma unroll
        for (int r = 0; r < 8; r++) { a += rs_[r][tid]; b += rq_[r][tid]; }
        atomicAdd(&g_sum[tid], a);
        atomicAdd(&g_ssq[tid], b);
    }
}

// =================================================================================
// Kernel E: BatchNorm normalize.
// =================================================================================
__global__ __launch_bounds__(256) void bn_kernel(
    const float* __restrict__ gamma, const float* __restrict__ beta,
    float* __restrict__ out)
{
    int idx = blockIdx.x * 256 + threadIdx.x;
    if (idx >= N_NODES * 32) return;
    int c4 = idx & 31;
    const float inv_n = 1.f / (float)N_NODES;

    float4 h  = *(const float4*)&g_h[(size_t)idx * 4];
    float4 sm = *(const float4*)&g_sum[c4 * 4];
    float4 sq = *(const float4*)&g_ssq[c4 * 4];
    float4 ga = *(const float4*)&gamma[c4 * 4];
    float4 be = *(const float4*)&beta[c4 * 4];

    float4 o;
    {
        float mean = sm.x * inv_n; float var = sq.x * inv_n - mean * mean;
        o.x = ga.x * (h.x - mean) * rsqrtf(var + BN_EPS) + be.x;
    }
    {
        float mean = sm.y * inv_n; float var = sq.y * inv_n - mean * mean;
        o.y = ga.y * (h.y - mean) * rsqrtf(var + BN_EPS) + be.y;
    }
    {
        float mean = sm.z * inv_n; float var = sq.z * inv_n - mean * mean;
        o.z = ga.z * (h.z - mean) * rsqrtf(var + BN_EPS) + be.z;
    }
    {
        float mean = sm.w * inv_n; float var = sq.w * inv_n - mean * mean;
        o.w = ga.w * (h.w - mean) * rsqrtf(var + BN_EPS) + be.w;
    }
    *(float4*)&out[(size_t)idx * 4] = o;
}

// =================================================================================
extern "C" void kernel_launch(void* const* d_in, const int* in_sizes, int n_in,
                              void* d_out, int out_size)
{
    const float* x     = (const float*)d_in[0];
    const void*  ei    = d_in[1];
    const float* W_msg = (const float*)d_in[2];
    const float* b_msg = (const float*)d_in[3];
    const float* W_att = (const float*)d_in[4];
    const float* b_att = (const float*)d_in[5];
    const float* W_ih  = (const float*)d_in[6];
    const float* b_ih  = (const float*)d_in[7];
    const float* W_hh  = (const float*)d_in[8];
    const float* b_hh  = (const float*)d_in[9];
    const float* gamma = (const float*)d_in[10];
    const float* beta  = (const float*)d_in[11];
    float* out = (float*)d_out;

    const int E = in_sizes[1] / 2;
    const int QUADS = (NT + TPB - 1) / TPB;   // 98

    static int smem_set = 0;
    if (!smem_set) {
        cudaFuncSetAttribute(gemm_main_kernel,
                             cudaFuncAttributeMaxDynamicSharedMemorySize, SMEM_GEMM);
        cudaFuncSetAttribute(gemm_msg_kernel,
                             cudaFuncAttributeMaxDynamicSharedMemorySize, SMEM_GEMM);
        smem_set = 1;
    }

    detect_kernel<<<1, 1>>>(ei, E);
    node_pre_kernel<<<NP / 64, 256>>>(x, W_att);
    convert_w_kernel<<<(CVT_W_Q + 255) / 256, 256>>>(W_ih, W_hh, W_msg);
    gemm_msg_kernel<<<QUADS, 256, SMEM_GEMM>>>(b_msg);
    hist_kernel<<<(E + 255) / 256, 256>>>(ei, E);
    scan_a_kernel<<<NSCAN / 256, 256>>>();
    scan_b_kernel<<<1, 256>>>();
    scan_c_kernel<<<NSCAN / 256, 256>>>();
    scatter_kernel<<<(E + 255) / 256, 256>>>(ei, E);
    gather_kernel<<<(NP + 7) / 8, 256>>>(b_att);
    gemm_main_kernel<<<dim3(6, QUADS), 256, SMEM_GEMM>>>(b_ih, b_hh);
    gru_kernel<<<NP / 128, 256>>>(x);
    bn_kernel<<<(N_NODES * 32 + 255) / 256, 256>>>(gamma, beta, out);
}